// round 10
// baseline (speedup 1.0000x reference)
#include <cuda_runtime.h>
#include <cuda_bf16.h>
#include <math.h>
#include <stdint.h>

#define EE   300
#define HH   256
#define G4   1024
#define H2   512
#define H8   2048
#define BB   64
#define LQ   64
#define LC   512

__device__ float g_qemb[(size_t)BB * LQ * EE];
__device__ float g_cemb[(size_t)BB * LC * EE];
__device__ float g_xw  [(size_t)2 * BB * LC * G4];
__device__ float g_qout[(size_t)BB * LQ * H2];
__device__ float g_cout[(size_t)BB * LC * H2];
__device__ float g_S   [(size_t)BB * LC * LQ];
__device__ float g_smax[(size_t)BB * LC];
__device__ float g_batt[(size_t)BB * LC];
__device__ float g_cw  [(size_t)BB * LC];
__device__ float g_qw  [(size_t)BB * LQ];
__device__ float g_c2q [(size_t)BB * LC * H2];
__device__ float g_q2c [(size_t)BB * H2];
__device__ float g_G   [(size_t)BB * LC * H8];
__device__ float g_M   [(size_t)BB * LC * H2];
__device__ float g_h   [(size_t)2 * HH * BB];
__device__ float g_wcvt[(size_t)2 * G4 * H8];
__device__ unsigned g_bar_cnt = 0;
__device__ unsigned g_bar_gen = 0;

__device__ __forceinline__ float sigmoidf_(float x) { return 1.f / (1.f + expf(-x)); }

__device__ __forceinline__ uint32_t f2tf32(float x)
{
    uint32_t r;
    asm("cvt.rna.tf32.f32 %0, %1;" : "=r"(r) : "f"(x));
    return r;
}
__device__ __forceinline__ float rtf(float x) { return __uint_as_float(f2tf32(x)); }

__device__ __forceinline__ void grid_barrier(unsigned nb)
{
    __threadfence();
    __syncthreads();
    if (threadIdx.x == 0) {
        unsigned g = *(volatile unsigned*)&g_bar_gen;
        if (atomicAdd(&g_bar_cnt, 1u) == nb - 1u) {
            g_bar_cnt = 0;
            __threadfence();
            atomicAdd(&g_bar_gen, 1u);
        } else {
            while (*(volatile unsigned*)&g_bar_gen == g) { }
        }
    }
    __syncthreads();
    __threadfence();
}

__device__ __forceinline__ void cp16(uint32_t dst, const void* src)
{
    asm volatile("cp.async.cg.shared.global [%0], [%1], 16;" :: "r"(dst), "l"(src));
}
__device__ __forceinline__ uint32_t smem_u32(const void* p)
{
    uint32_t a;
    asm("{ .reg .u64 t; cvta.to.shared.u64 t, %1; cvt.u32.u64 %0, t; }" : "=r"(a) : "l"(p));
    return a;
}

// ---------------------------------------------------------------------------
__global__ void gather_emb(const int* __restrict__ tok, const float* __restrict__ emb,
                           float* __restrict__ out, int total)
{
    int i = blockIdx.x * blockDim.x + threadIdx.x;
    if (i >= total) return;
    int row = i / EE;
    int e   = i - row * EE;
    out[i] = rtf(emb[(size_t)tok[row] * EE + e]);
}

__global__ void cvt_tf32(const float* __restrict__ in, float* __restrict__ out, int n)
{
    int i = blockIdx.x * blockDim.x + threadIdx.x;
    if (i < n) out[i] = rtf(in[i]);
}

// ---------------------------------------------------------------------------
// tf32 mma.sync GEMM v3: C[M,N]=A[M,K]*B[N,K]^T + bias.
// CTA tile 128x256, 8 warps (2m x 4n), warp tile 64x64, BK=32,
// cp.async 2-stage pipeline. A,B pre-rounded to tf32.
// M%128==0, N%256==0, K%4==0. 256 threads.
// ---------------------------------------------------------------------------
#define SROW 36
#define ATILE (128 * SROW)               // 4608 floats
#define BTILE (256 * SROW)               // 9216 floats
#define STAGE (ATILE + BTILE)            // 13824 floats
#define GEMM_SMEM (2 * STAGE * (int)sizeof(float))   // 110592 B

__device__ __forceinline__ void fill_tile(uint32_t sA, uint32_t sB,
                                          const float* __restrict__ A,
                                          const float* __restrict__ B,
                                          int bm, int bn, int K, int k0, int tid)
{
#pragma unroll
    for (int i = 0; i < 4; ++i) {        // A: 128 rows x 8 chunks = 1024
        int idx = tid + i * 256;
        int row = idx >> 3, c4 = idx & 7;
        int k = k0 + c4 * 4;
        uint32_t da = sA + (row * SROW + c4 * 4) * 4;
        if (k + 4 <= K) cp16(da, &A[(size_t)(bm + row) * K + k]);
        else asm volatile("st.shared.v4.b32 [%0], {%1,%1,%1,%1};" :: "r"(da), "r"(0) : "memory");
    }
#pragma unroll
    for (int i = 0; i < 8; ++i) {        // B: 256 rows x 8 chunks = 2048
        int idx = tid + i * 256;
        int row = idx >> 3, c4 = idx & 7;
        int k = k0 + c4 * 4;
        uint32_t db = sB + (row * SROW + c4 * 4) * 4;
        if (k + 4 <= K) cp16(db, &B[(size_t)(bn + row) * K + k]);
        else asm volatile("st.shared.v4.b32 [%0], {%1,%1,%1,%1};" :: "r"(db), "r"(0) : "memory");
    }
}

__global__ void __launch_bounds__(256)
gemm_tf32(const float* __restrict__ A, const float* __restrict__ B,
          const float* __restrict__ bias, float* __restrict__ C,
          int M, int N, int K)
{
    extern __shared__ float sh[];        // [2][STAGE]
    const int tid  = threadIdx.x;
    const int lane = tid & 31;
    const int warp = tid >> 5;
    const int g = lane >> 2, t = lane & 3;
    const int m0 = (warp & 1) * 64;
    const int n0 = (warp >> 1) * 64;
    const int bm = blockIdx.y * 128;
    const int bn = blockIdx.x * 256;
    const uint32_t sb = smem_u32(sh);

    float acc[4][8][4];
#pragma unroll
    for (int mi = 0; mi < 4; ++mi)
#pragma unroll
        for (int ni = 0; ni < 8; ++ni)
#pragma unroll
            for (int k = 0; k < 4; ++k) acc[mi][ni][k] = 0.f;

    const int nk = (K + 31) >> 5;
    const uint32_t stage_b = STAGE * 4;

    fill_tile(sb, sb + ATILE * 4, A, B, bm, bn, K, 0, tid);
    asm volatile("cp.async.commit_group;" ::: "memory");

    int buf = 0;
    for (int kt = 0; kt < nk; ++kt) {
        if (kt + 1 < nk) {
            fill_tile(sb + (buf ^ 1) * stage_b, sb + (buf ^ 1) * stage_b + ATILE * 4,
                      A, B, bm, bn, K, (kt + 1) * 32, tid);
            asm volatile("cp.async.commit_group;" ::: "memory");
            asm volatile("cp.async.wait_group 1;" ::: "memory");
        } else {
            asm volatile("cp.async.wait_group 0;" ::: "memory");
        }
        __syncthreads();

        const float* Ab = sh + buf * STAGE;
        const float* Bb = Ab + ATILE;
#pragma unroll
        for (int kk = 0; kk < 32; kk += 8) {
            uint32_t af[4][4];
#pragma unroll
            for (int mi = 0; mi < 4; ++mi) {
                const float* ap = Ab + (m0 + mi * 16) * SROW + kk;
                af[mi][0] = __float_as_uint(ap[g * SROW + t]);
                af[mi][1] = __float_as_uint(ap[(g + 8) * SROW + t]);
                af[mi][2] = __float_as_uint(ap[g * SROW + t + 4]);
                af[mi][3] = __float_as_uint(ap[(g + 8) * SROW + t + 4]);
            }
            uint32_t bf[8][2];
#pragma unroll
            for (int ni = 0; ni < 8; ++ni) {
                const float* bp = Bb + (n0 + ni * 8) * SROW + kk;
                bf[ni][0] = __float_as_uint(bp[g * SROW + t]);
                bf[ni][1] = __float_as_uint(bp[g * SROW + t + 4]);
            }
#pragma unroll
            for (int mi = 0; mi < 4; ++mi)
#pragma unroll
                for (int ni = 0; ni < 8; ++ni)
                    asm volatile(
                        "mma.sync.aligned.m16n8k8.row.col.f32.tf32.tf32.f32 "
                        "{%0,%1,%2,%3}, {%4,%5,%6,%7}, {%8,%9}, {%0,%1,%2,%3};\n"
                        : "+f"(acc[mi][ni][0]), "+f"(acc[mi][ni][1]),
                          "+f"(acc[mi][ni][2]), "+f"(acc[mi][ni][3])
                        : "r"(af[mi][0]), "r"(af[mi][1]), "r"(af[mi][2]), "r"(af[mi][3]),
                          "r"(bf[ni][0]), "r"(bf[ni][1]));
        }
        __syncthreads();
        buf ^= 1;
    }

#pragma unroll
    for (int mi = 0; mi < 4; ++mi) {
#pragma unroll
        for (int ni = 0; ni < 8; ++ni) {
            int row0 = bm + m0 + mi * 16 + g;
            int col  = bn + n0 + ni * 8 + t * 2;
            float2 bv = make_float2(0.f, 0.f);
            if (bias) bv = *(const float2*)&bias[col];
            *(float2*)&C[(size_t)row0 * N + col] =
                make_float2(acc[mi][ni][0] + bv.x, acc[mi][ni][1] + bv.y);
            *(float2*)&C[(size_t)(row0 + 8) * N + col] =
                make_float2(acc[mi][ni][2] + bv.x, acc[mi][ni][3] + bv.y);
        }
    }
}

// ---------------------------------------------------------------------------
// Persistent BiLSTM scan — exact R3 version (best known).
// ---------------------------------------------------------------------------
__global__ void lstm_scan(const float* __restrict__ xW, const float* __restrict__ Whh,
                          float* __restrict__ out, int T)
{
    extern __shared__ float sh[];
    float* h_sh   = sh;
    float* whh_sh = sh + HH * BB;
    float* xw_sh  = whh_sh + 16 * HH;

    const int tid = threadIdx.x;
    const int dir = blockIdx.x >> 6;
    const int jc  = blockIdx.x & 63;
    const int j0  = jc * 4;
    const int b   = tid & 63;
    const int jj  = tid >> 6;
    const int j   = j0 + jj;

    const float* WhhD = Whh + (size_t)dir * G4 * HH;
    for (int idx = tid; idx < 16 * 64; idx += 256) {
        int row = idx >> 6;
        int k4  = (idx & 63) << 2;
        int g = row >> 2, jr = row & 3;
        float4 v = *(const float4*)&WhhD[(size_t)(g * HH + j0 + jr) * HH + k4];
        *(float4*)&whh_sh[row * HH + k4] = v;
    }

    const float* xWD = xW + (size_t)dir * BB * T * G4;
    float*       hD  = g_h + (size_t)dir * HH * BB;

    float creg = 0.f;
    const int lb = tid >> 2, lg = tid & 3;

    for (int s = 0; s < T; ++s) {
        const int tt = dir ? (T - 1 - s) : s;
        {
            float4 v = *(const float4*)&xWD[((size_t)lb * T + tt) * G4 + lg * HH + j0];
            *(float4*)&xw_sh[(lb * 4 + lg) * 4] = v;
        }
        if (s > 0) {
#pragma unroll
            for (int i = 0; i < 16; ++i) {
                int idx4 = tid + i * 256;
                float4 v = __ldcg((const float4*)hD + idx4);
                ((float4*)h_sh)[idx4] = v;
            }
        }
        __syncthreads();

        float a0 = xw_sh[b * 16 + 0 * 4 + jj];
        float a1 = xw_sh[b * 16 + 1 * 4 + jj];
        float a2 = xw_sh[b * 16 + 2 * 4 + jj];
        float a3 = xw_sh[b * 16 + 3 * 4 + jj];

        if (s > 0) {
            const float* w0 = &whh_sh[(0 * 4 + jj) * HH];
            const float* w1 = &whh_sh[(1 * 4 + jj) * HH];
            const float* w2 = &whh_sh[(2 * 4 + jj) * HH];
            const float* w3 = &whh_sh[(3 * 4 + jj) * HH];
#pragma unroll 8
            for (int k = 0; k < HH; k += 4) {
                float h0 = h_sh[(k + 0) * BB + b];
                float h1 = h_sh[(k + 1) * BB + b];
                float h2 = h_sh[(k + 2) * BB + b];
                float h3 = h_sh[(k + 3) * BB + b];
                float4 v0 = *(const float4*)&w0[k];
                float4 v1 = *(const float4*)&w1[k];
                float4 v2 = *(const float4*)&w2[k];
                float4 v3 = *(const float4*)&w3[k];
                a0 += v0.x * h0; a0 += v0.y * h1; a0 += v0.z * h2; a0 += v0.w * h3;
                a1 += v1.x * h0; a1 += v1.y * h1; a1 += v1.z * h2; a1 += v1.w * h3;
                a2 += v2.x * h0; a2 += v2.y * h1; a2 += v2.z * h2; a2 += v2.w * h3;
                a3 += v3.x * h0; a3 += v3.y * h1; a3 += v3.z * h2; a3 += v3.w * h3;
            }
        }

        float ig = sigmoidf_(a0);
        float fg = sigmoidf_(a1);
        float gg = tanhf(a2);
        float og = sigmoidf_(a3);
        creg = fg * creg + ig * gg;
        float hh = og * tanhf(creg);

        __stcg(&hD[j * BB + b], hh);
        out[((size_t)b * T + tt) * H2 + dir * HH + j] = hh;

        if (s + 1 < T) grid_barrier(gridDim.x);
    }
}

// ---------------------------------------------------------------------------
__global__ void rowdot(const float* __restrict__ A, const float* __restrict__ w,
                       const float* __restrict__ bias, float* __restrict__ out, int rows)
{
    int gw = (blockIdx.x * blockDim.x + threadIdx.x) >> 5;
    int lane = threadIdx.x & 31;
    if (gw >= rows) return;
    const float* row = A + (size_t)gw * H2;
    float s = 0.f;
#pragma unroll
    for (int i = 0; i < 16; ++i) s += row[lane + i * 32] * w[lane + i * 32];
#pragma unroll
    for (int off = 16; off; off >>= 1) s += __shfl_xor_sync(0xffffffffu, s, off);
    if (lane == 0) out[gw] = s + (bias ? bias[0] : 0.f);
}

__global__ void __launch_bounds__(256)
attn_S(const float* __restrict__ c_out, const float* __restrict__ q_out,
       const float* __restrict__ sim_w, const float* __restrict__ sim_b,
       const float* __restrict__ cw, const float* __restrict__ qw,
       float* __restrict__ S)
{
    __shared__ float As[16][68];
    __shared__ float Bs[16][68];
    const int b = blockIdx.y, cc0 = blockIdx.x * 64;
    const float* A  = c_out + ((size_t)b * LC + cc0) * H2;
    const float* Bq = q_out + (size_t)b * LQ * H2;
    const float* wcq = sim_w + 2 * H2;
    const int tid = threadIdx.x;
    const int lr = tid >> 2, lk4 = (tid & 3) * 4;
    const int tx = tid & 15, ty = tid >> 4;
    float acc[4][4];
#pragma unroll
    for (int i = 0; i < 4; ++i)
#pragma unroll
        for (int j = 0; j < 4; ++j) acc[i][j] = 0.f;

    for (int k0 = 0; k0 < H2; k0 += 16) {
        float4 va = *(const float4*)&A[(size_t)lr * H2 + k0 + lk4];
        float4 wv = *(const float4*)&wcq[k0 + lk4];
        As[lk4 + 0][lr] = va.x * wv.x;
        As[lk4 + 1][lr] = va.y * wv.y;
        As[lk4 + 2][lr] = va.z * wv.z;
        As[lk4 + 3][lr] = va.w * wv.w;
        float4 vb = *(const float4*)&Bq[(size_t)lr * H2 + k0 + lk4];
        Bs[lk4 + 0][lr] = vb.x;
        Bs[lk4 + 1][lr] = vb.y;
        Bs[lk4 + 2][lr] = vb.z;
        Bs[lk4 + 3][lr] = vb.w;
        __syncthreads();
#pragma unroll
        for (int k = 0; k < 16; ++k) {
            float4 av = *(const float4*)&As[k][ty * 4];
            float4 bv = *(const float4*)&Bs[k][tx * 4];
            float am[4] = {av.x, av.y, av.z, av.w};
            float bn[4] = {bv.x, bv.y, bv.z, bv.w};
#pragma unroll
            for (int i = 0; i < 4; ++i)
#pragma unroll
                for (int j = 0; j < 4; ++j) acc[i][j] += am[i] * bn[j];
        }
        __syncthreads();
    }
    float sb = sim_b[0];
#pragma unroll
    for (int i = 0; i < 4; ++i) {
        int cc = cc0 + ty * 4 + i;
        float cwv = cw[b * LC + cc];
#pragma unroll
        for (int j = 0; j < 4; ++j) {
            int qq = tx * 4 + j;
            S[((size_t)b * LC + cc) * LQ + qq] = acc[i][j] + cwv + qw[b * LQ + qq] + sb;
        }
    }
}

__global__ void softmax64(float* __restrict__ S, float* __restrict__ smax, int rows)
{
    int gw = (blockIdx.x * blockDim.x + threadIdx.x) >> 5;
    int lane = threadIdx.x & 31;
    if (gw >= rows) return;
    float* row = S + (size_t)gw * LQ;
    float v0 = row[lane], v1 = row[lane + 32];
    float m = fmaxf(v0, v1);
#pragma unroll
    for (int off = 16; off; off >>= 1) m = fmaxf(m, __shfl_xor_sync(0xffffffffu, m, off));
    float e0 = expf(v0 - m), e1 = expf(v1 - m);
    float s = e0 + e1;
#pragma unroll
    for (int off = 16; off; off >>= 1) s += __shfl_xor_sync(0xffffffffu, s, off);
    float inv = 1.f / s;
    row[lane] = e0 * inv;
    row[lane + 32] = e1 * inv;
    if (lane == 0) smax[gw] = m;
}

__global__ void softmax512(const float* __restrict__ in, float* __restrict__ outv)
{
    __shared__ float red[16];
    int b = blockIdx.x, tid = threadIdx.x;
    float v = in[(size_t)b * LC + tid];
    float m = v;
#pragma unroll
    for (int off = 16; off; off >>= 1) m = fmaxf(m, __shfl_xor_sync(0xffffffffu, m, off));
    if ((tid & 31) == 0) red[tid >> 5] = m;
    __syncthreads();
    if (tid == 0) {
        float x = red[0];
        for (int i = 1; i < 16; ++i) x = fmaxf(x, red[i]);
        red[0] = x;
    }
    __syncthreads();
    m = red[0];
    __syncthreads();
    float e = expf(v - m);
    float s = e;
#pragma unroll
    for (int off = 16; off; off >>= 1) s += __shfl_xor_sync(0xffffffffu, s, off);
    if ((tid & 31) == 0) red[tid >> 5] = s;
    __syncthreads();
    if (tid == 0) {
        float x = 0.f;
        for (int i = 0; i < 16; ++i) x += red[i];
        red[0] = x;
    }
    __syncthreads();
    outv[(size_t)b * LC + tid] = e / red[0];
}

__global__ void __launch_bounds__(256)
attn_c2q(const float* __restrict__ a, const float* __restrict__ q_out,
         float* __restrict__ c2q)
{
    __shared__ float As[16][68];
    __shared__ float Bs[16][68];
    const int b = blockIdx.z, cc0 = blockIdx.y * 64, h0 = blockIdx.x * 64;
    const float* A = a + ((size_t)b * LC + cc0) * LQ;
    const float* B = q_out + (size_t)b * LQ * H2;
    const int tid = threadIdx.x;
    const int lr = tid >> 2, lk4 = (tid & 3) * 4;
    const int bk = tid >> 4, bn4 = (tid & 15) * 4;
    const int tx = tid & 15, ty = tid >> 4;
    float acc[4][4];
#pragma unroll
    for (int i = 0; i < 4; ++i)
#pragma unroll
        for (int j = 0; j < 4; ++j) acc[i][j] = 0.f;

    for (int k0 = 0; k0 < LQ; k0 += 16) {
        float4 va = *(const float4*)&A[(size_t)lr * LQ + k0 + lk4];
        As[lk4 + 0][lr] = va.x;
        As[lk4 + 1][lr] = va.y;
        As[lk4 + 2][lr] = va.z;
        As[lk4 + 3][lr] = va.w;
        float4 vb = *(const float4*)&B[(size_t)(k0 + bk) * H2 + h0 + bn4];
        *(float4*)&Bs[bk][bn4] = vb;
        __syncthreads();
#pragma unroll
        for (int k = 0; k < 16; ++k) {
            float4 av = *(const float4*)&As[k][ty * 4];
            float4 bv = *(const float4*)&Bs[k][tx * 4];
            float am[4] = {av.x, av.y, av.z, av.w};
            float bn[4] = {bv.x, bv.y, bv.z, bv.w};
#pragma unroll
            for (int i = 0; i < 4; ++i)
#pragma unroll
                for (int j = 0; j < 4; ++j) acc[i][j] += am[i] * bn[j];
        }
        __syncthreads();
    }
#pragma unroll
    for (int i = 0; i < 4; ++i)
#pragma unroll
        for (int j = 0; j < 4; ++j)
            c2q[((size_t)b * LC + cc0 + ty * 4 + i) * H2 + h0 + tx * 4 + j] = acc[i][j];
}

__global__ void attn_q2c(const float* __restrict__ batt, const float* __restrict__ c_out,
                         float* __restrict__ q2c)
{
    int b = blockIdx.y;
    int h = blockIdx.x * 128 + threadIdx.x;
    const float* C = c_out + (size_t)b * LC * H2;
    const float* w = batt + (size_t)b * LC;
    float acc = 0.f;
    for (int cc = 0; cc < LC; ++cc) acc += w[cc] * C[(size_t)cc * H2 + h];
    q2c[(size_t)b * H2 + h] = acc;
}

__global__ void build_G(const float* __restrict__ c_out, const float* __restrict__ c2q,
                        const float* __restrict__ q2c, float* __restrict__ G)
{
    size_t i = (size_t)blockIdx.x * blockDim.x + threadIdx.x;
    const size_t total = (size_t)BB * LC * (H2 / 4);
    if (i >= total) return;
    int h4 = (int)(i % (H2 / 4));
    size_t r = i / (H2 / 4);
    int b = (int)(r / LC);
    float4 co = ((const float4*)c_out)[r * (H2 / 4) + h4];
    float4 cq = ((const float4*)c2q)[r * (H2 / 4) + h4];
    float4 q2 = ((const float4*)q2c)[(size_t)b * (H2 / 4) + h4];
    float4* Gr = (float4*)(G + r * H8);
    Gr[h4] = make_float4(rtf(co.x), rtf(co.y), rtf(co.z), rtf(co.w));
    Gr[(H2 / 4) + h4] = make_float4(rtf(cq.x), rtf(cq.y), rtf(cq.z), rtf(cq.w));
    Gr[2 * (H2 / 4) + h4] = make_float4(rtf(co.x * cq.x), rtf(co.y * cq.y),
                                        rtf(co.z * cq.z), rtf(co.w * cq.w));
    Gr[3 * (H2 / 4) + h4] = make_float4(rtf(co.x * q2.x), rtf(co.y * q2.y),
                                        rtf(co.z * q2.z), rtf(co.w * q2.w));
}

// ---------------------------------------------------------------------------
extern "C" void kernel_launch(void* const* d_in, const int* in_sizes, int n_in,
                              void* d_out, int out_size)
{
    const int*   q       = (const int*)  d_in[0];
    const int*   c       = (const int*)  d_in[1];
    const float* emb     = (const float*)d_in[2];
    const float* Wih_q   = (const float*)d_in[3];
    const float* Whh_q   = (const float*)d_in[4];
    const float* b_q     = (const float*)d_in[5];
    const float* Wih_c   = (const float*)d_in[6];
    const float* Whh_c   = (const float*)d_in[7];
    const float* b_c     = (const float*)d_in[8];
    const float* Wih_m   = (const float*)d_in[9];
    const float* Whh_m   = (const float*)d_in[10];
    const float* b_m     = (const float*)d_in[11];
    const float* sim_w   = (const float*)d_in[12];
    const float* sim_b   = (const float*)d_in[13];
    const float* start_w = (const float*)d_in[14];
    const float* start_b = (const float*)d_in[15];
    const float* end_w   = (const float*)d_in[16];
    const float* end_b   = (const float*)d_in[17];
    float* out = (float*)d_out;

    float *qemb, *cemb, *xw, *qout, *cout, *S, *smax, *batt, *cw, *qw, *c2q, *q2c, *G, *M, *wcvt;
    cudaGetSymbolAddress((void**)&qemb, g_qemb);
    cudaGetSymbolAddress((void**)&cemb, g_cemb);
    cudaGetSymbolAddress((void**)&xw,   g_xw);
    cudaGetSymbolAddress((void**)&qout, g_qout);
    cudaGetSymbolAddress((void**)&cout, g_cout);
    cudaGetSymbolAddress((void**)&S,    g_S);
    cudaGetSymbolAddress((void**)&smax, g_smax);
    cudaGetSymbolAddress((void**)&batt, g_batt);
    cudaGetSymbolAddress((void**)&cw,   g_cw);
    cudaGetSymbolAddress((void**)&qw,   g_qw);
    cudaGetSymbolAddress((void**)&c2q,  g_c2q);
    cudaGetSymbolAddress((void**)&q2c,  g_q2c);
    cudaGetSymbolAddress((void**)&G,    g_G);
    cudaGetSymbolAddress((void**)&M,    g_M);
    cudaGetSymbolAddress((void**)&wcvt, g_wcvt);

    const int lstm_smem = (HH * BB + 16 * HH + 64 * 16) * (int)sizeof(float);
    cudaFuncSetAttribute(lstm_scan, cudaFuncAttributeMaxDynamicSharedMemorySize, lstm_smem);
    cudaFuncSetAttribute(gemm_tf32, cudaFuncAttributeMaxDynamicSharedMemorySize, GEMM_SMEM);

    gather_emb<<<(BB * LQ * EE + 255) / 256, 256>>>(q, emb, qemb, BB * LQ * EE);
    gather_emb<<<(BB * LC * EE + 255) / 256, 256>>>(c, emb, cemb, BB * LC * EE);

    // q BiLSTM
    cvt_tf32<<<(2 * G4 * EE + 255) / 256, 256>>>(Wih_q, wcvt, 2 * G4 * EE);
    for (int d = 0; d < 2; ++d)
        gemm_tf32<<<dim3(G4 / 256, (BB * LQ) / 128), 256, GEMM_SMEM>>>(
            qemb, wcvt + (size_t)d * G4 * EE, b_q + (size_t)d * G4,
            xw + (size_t)d * BB * LQ * G4, BB * LQ, G4, EE);
    lstm_scan<<<128, 256, lstm_smem>>>(xw, Whh_q, qout, LQ);

    // c BiLSTM
    cvt_tf32<<<(2 * G4 * EE + 255) / 256, 256>>>(Wih_c, wcvt, 2 * G4 * EE);
    for (int d = 0; d < 2; ++d)
        gemm_tf32<<<dim3(G4 / 256, (BB * LC) / 128), 256, GEMM_SMEM>>>(
            cemb, wcvt + (size_t)d * G4 * EE, b_c + (size_t)d * G4,
            xw + (size_t)d * BB * LC * G4, BB * LC, G4, EE);
    lstm_scan<<<128, 256, lstm_smem>>>(xw, Whh_c, cout, LC);

    // attention
    rowdot<<<(BB * LC) / 8, 256>>>(cout, sim_w, nullptr, cw, BB * LC);
    rowdot<<<(BB * LQ) / 8, 256>>>(qout, sim_w + H2, nullptr, qw, BB * LQ);
    attn_S<<<dim3(LC / 64, BB), 256>>>(cout, qout, sim_w, sim_b, cw, qw, S);
    softmax64<<<(BB * LC) / 8, 256>>>(S, smax, BB * LC);
    softmax512<<<BB, 512>>>(smax, batt);
    attn_c2q<<<dim3(H2 / 64, LC / 64, BB), 256>>>(S, qout, c2q);
    attn_q2c<<<dim3(H2 / 128, BB), 128>>>(batt, cout, q2c);
    build_G<<<(int)(((size_t)BB * LC * (H2 / 4) + 255) / 256), 256>>>(cout, c2q, q2c, G);

    // modeling BiLSTM
    cvt_tf32<<<(2 * G4 * H8 + 255) / 256, 256>>>(Wih_m, wcvt, 2 * G4 * H8);
    for (int d = 0; d < 2; ++d)
        gemm_tf32<<<dim3(G4 / 256, (BB * LC) / 128), 256, GEMM_SMEM>>>(
            G, wcvt + (size_t)d * G4 * H8, b_m + (size_t)d * G4,
            xw + (size_t)d * BB * LC * G4, BB * LC, G4, H8);
    lstm_scan<<<128, 256, lstm_smem>>>(xw, Whh_m, M, LC);

    rowdot<<<(BB * LC) / 8, 256>>>(M, start_w, start_b, out, BB * LC);
    rowdot<<<(BB * LC) / 8, 256>>>(M, end_w, end_b, out + (size_t)BB * LC, BB * LC);
}

// round 11
// speedup vs baseline: 1.2287x; 1.2287x over previous
#include <cuda_runtime.h>
#include <cuda_bf16.h>
#include <math.h>
#include <stdint.h>

#define EE   300
#define HH   256
#define G4   1024
#define H2   512
#define H8   2048
#define BB   64
#define LQ   64
#define LC   512

__device__ float g_qemb[(size_t)BB * LQ * EE];
__device__ float g_cemb[(size_t)BB * LC * EE];
__device__ float g_xw  [(size_t)2 * BB * LC * G4];
__device__ float g_qout[(size_t)BB * LQ * H2];
__device__ float g_cout[(size_t)BB * LC * H2];
__device__ float g_S   [(size_t)BB * LC * LQ];
__device__ float g_smax[(size_t)BB * LC];
__device__ float g_batt[(size_t)BB * LC];
__device__ float g_cw  [(size_t)BB * LC];
__device__ float g_qw  [(size_t)BB * LQ];
__device__ float g_c2q [(size_t)BB * LC * H2];
__device__ float g_q2c [(size_t)BB * H2];
__device__ float g_G   [(size_t)BB * LC * H8];
__device__ float g_M   [(size_t)BB * LC * H2];
__device__ float g_h   [(size_t)2 * HH * BB];
__device__ float g_wcvt[(size_t)2 * G4 * H8];
__device__ float g_whh [(size_t)2 * G4 * HH];
__device__ unsigned g_bar_cnt = 0;
__device__ unsigned g_bar_gen = 0;

__device__ __forceinline__ float sigmoidf_(float x) { return 1.f / (1.f + expf(-x)); }

__device__ __forceinline__ uint32_t f2tf32(float x)
{
    uint32_t r;
    asm("cvt.rna.tf32.f32 %0, %1;" : "=r"(r) : "f"(x));
    return r;
}
__device__ __forceinline__ float rtf(float x) { return __uint_as_float(f2tf32(x)); }

__device__ __forceinline__ void grid_barrier(unsigned nb)
{
    __threadfence();
    __syncthreads();
    if (threadIdx.x == 0) {
        unsigned g = *(volatile unsigned*)&g_bar_gen;
        if (atomicAdd(&g_bar_cnt, 1u) == nb - 1u) {
            g_bar_cnt = 0;
            __threadfence();
            atomicAdd(&g_bar_gen, 1u);
        } else {
            while (*(volatile unsigned*)&g_bar_gen == g) { }
        }
    }
    __syncthreads();
    __threadfence();
}

__device__ __forceinline__ void cp16(uint32_t dst, const void* src)
{
    asm volatile("cp.async.cg.shared.global [%0], [%1], 16;" :: "r"(dst), "l"(src));
}
__device__ __forceinline__ uint32_t smem_u32(const void* p)
{
    uint32_t a;
    asm("{ .reg .u64 t; cvta.to.shared.u64 t, %1; cvt.u32.u64 %0, t; }" : "=r"(a) : "l"(p));
    return a;
}

// ---------------------------------------------------------------------------
__global__ void gather_emb(const int* __restrict__ tok, const float* __restrict__ emb,
                           float* __restrict__ out, int total)
{
    int i = blockIdx.x * blockDim.x + threadIdx.x;
    if (i >= total) return;
    int row = i / EE;
    int e   = i - row * EE;
    out[i] = rtf(emb[(size_t)tok[row] * EE + e]);
}

__global__ void cvt_tf32(const float* __restrict__ in, float* __restrict__ out, int n)
{
    int i = blockIdx.x * blockDim.x + threadIdx.x;
    if (i < n) out[i] = rtf(in[i]);
}

// ---------------------------------------------------------------------------
// tf32 mma.sync GEMM v2 (best measured: ~94 TF/s): C=A[M,K]*B[N,K]^T + bias.
// CTA 128x128, 4 warps, warp tile 64x64, BK=32, cp.async 2-stage.
// ---------------------------------------------------------------------------
#define SROW 36
#define STILE (128 * SROW)
#define GEMM_SMEM (4 * STILE * (int)sizeof(float))   // 73728 B

__device__ __forceinline__ void fill_tile(uint32_t sA, uint32_t sB,
                                          const float* __restrict__ A,
                                          const float* __restrict__ B,
                                          int bm, int bn, int K, int k0, int tid)
{
#pragma unroll
    for (int i = 0; i < 8; ++i) {
        int idx = tid + i * 128;
        int row = idx >> 3, c4 = idx & 7;
        int k = k0 + c4 * 4;
        uint32_t da = sA + (row * SROW + c4 * 4) * 4;
        uint32_t db = sB + (row * SROW + c4 * 4) * 4;
        if (k + 4 <= K) {
            cp16(da, &A[(size_t)(bm + row) * K + k]);
            cp16(db, &B[(size_t)(bn + row) * K + k]);
        } else {
            asm volatile("st.shared.v4.b32 [%0], {%1,%1,%1,%1};" :: "r"(da), "r"(0) : "memory");
            asm volatile("st.shared.v4.b32 [%0], {%1,%1,%1,%1};" :: "r"(db), "r"(0) : "memory");
        }
    }
}

__global__ void __launch_bounds__(128)
gemm_tf32(const float* __restrict__ A, const float* __restrict__ B,
          const float* __restrict__ bias, float* __restrict__ C,
          int M, int N, int K)
{
    extern __shared__ float sh[];
    const int tid  = threadIdx.x;
    const int lane = tid & 31;
    const int warp = tid >> 5;
    const int g = lane >> 2, t = lane & 3;
    const int m0 = (warp & 1) * 64;
    const int n0 = (warp >> 1) * 64;
    const int bm = blockIdx.y * 128;
    const int bn = blockIdx.x * 128;
    const uint32_t sb = smem_u32(sh);

    float acc[4][8][4];
#pragma unroll
    for (int mi = 0; mi < 4; ++mi)
#pragma unroll
        for (int ni = 0; ni < 8; ++ni)
#pragma unroll
            for (int k = 0; k < 4; ++k) acc[mi][ni][k] = 0.f;

    const int nk = (K + 31) >> 5;
    const uint32_t stage_b = 2 * STILE * 4;

    fill_tile(sb, sb + STILE * 4, A, B, bm, bn, K, 0, tid);
    asm volatile("cp.async.commit_group;" ::: "memory");

    int buf = 0;
    for (int kt = 0; kt < nk; ++kt) {
        if (kt + 1 < nk) {
            fill_tile(sb + (buf ^ 1) * stage_b, sb + (buf ^ 1) * stage_b + STILE * 4,
                      A, B, bm, bn, K, (kt + 1) * 32, tid);
            asm volatile("cp.async.commit_group;" ::: "memory");
            asm volatile("cp.async.wait_group 1;" ::: "memory");
        } else {
            asm volatile("cp.async.wait_group 0;" ::: "memory");
        }
        __syncthreads();

        const float* Ab = sh + buf * 2 * STILE;
        const float* Bb = Ab + STILE;
#pragma unroll
        for (int kk = 0; kk < 32; kk += 8) {
            uint32_t af[4][4];
#pragma unroll
            for (int mi = 0; mi < 4; ++mi) {
                const float* ap = Ab + (m0 + mi * 16) * SROW + kk;
                af[mi][0] = __float_as_uint(ap[g * SROW + t]);
                af[mi][1] = __float_as_uint(ap[(g + 8) * SROW + t]);
                af[mi][2] = __float_as_uint(ap[g * SROW + t + 4]);
                af[mi][3] = __float_as_uint(ap[(g + 8) * SROW + t + 4]);
            }
            uint32_t bf[8][2];
#pragma unroll
            for (int ni = 0; ni < 8; ++ni) {
                const float* bp = Bb + (n0 + ni * 8) * SROW + kk;
                bf[ni][0] = __float_as_uint(bp[g * SROW + t]);
                bf[ni][1] = __float_as_uint(bp[g * SROW + t + 4]);
            }
#pragma unroll
            for (int mi = 0; mi < 4; ++mi)
#pragma unroll
                for (int ni = 0; ni < 8; ++ni)
                    asm volatile(
                        "mma.sync.aligned.m16n8k8.row.col.f32.tf32.tf32.f32 "
                        "{%0,%1,%2,%3}, {%4,%5,%6,%7}, {%8,%9}, {%0,%1,%2,%3};\n"
                        : "+f"(acc[mi][ni][0]), "+f"(acc[mi][ni][1]),
                          "+f"(acc[mi][ni][2]), "+f"(acc[mi][ni][3])
                        : "r"(af[mi][0]), "r"(af[mi][1]), "r"(af[mi][2]), "r"(af[mi][3]),
                          "r"(bf[ni][0]), "r"(bf[ni][1]));
        }
        __syncthreads();
        buf ^= 1;
    }

#pragma unroll
    for (int mi = 0; mi < 4; ++mi) {
#pragma unroll
        for (int ni = 0; ni < 8; ++ni) {
            int row0 = bm + m0 + mi * 16 + g;
            int col  = bn + n0 + ni * 8 + t * 2;
            float2 bv = make_float2(0.f, 0.f);
            if (bias) bv = *(const float2*)&bias[col];
            *(float2*)&C[(size_t)row0 * N + col] =
                make_float2(acc[mi][ni][0] + bv.x, acc[mi][ni][1] + bv.y);
            *(float2*)&C[(size_t)(row0 + 8) * N + col] =
                make_float2(acc[mi][ni][2] + bv.x, acc[mi][ni][3] + bv.y);
        }
    }
}

// ---------------------------------------------------------------------------
// BiLSTM scan with tensor-core recurrence.
// 64 blocks = 2 dirs x 32 chunks of 8 hidden units. 256 threads (8 warps).
// Per step: P[64b, 32 gate-rows] = h[64,256] @ W[32,256]^T via tf32 mma;
// Whh fragments persist in registers; h_sh [k][b] pad-72 (conflict-free);
// gate epilogue by 256 threads (cell state in regs). h stored tf32-rounded.
// Whh must be pre-rounded to tf32.
// ---------------------------------------------------------------------------
#define LPAD 72
#define SC_H   (HH * LPAD)              // 18432 floats
#define SC_XW  (SC_H + BB * 33)         // xw_sh [64][33]
#define SC_TOT (SC_XW + BB * 33)        // P_sh  [64][33]
#define SCAN_SMEM (SC_TOT * (int)sizeof(float))   // 90624 B

__global__ void __launch_bounds__(256)
lstm_scan(const float* __restrict__ xW, const float* __restrict__ Whh,
          float* __restrict__ out, int T)
{
    extern __shared__ float sh[];
    float* h_sh  = sh;                 // [256][72]
    float* xw_sh = sh + SC_H;          // [64][33]
    float* P_sh  = sh + SC_XW;         // [64][33]

    const int tid  = threadIdx.x;
    const int lane = tid & 31;
    const int warp = tid >> 5;
    const int g = lane >> 2, t = lane & 3;
    const int nt  = warp >> 1;         // gate 0..3
    const int mtp = warp & 1;          // m-tile pair {mtp, mtp+2}
    const int dir = blockIdx.x >> 5;
    const int j0  = (blockIdx.x & 31) * 8;

    // persistent Whh fragments: row = gate nt, unit j0+g  (pre-rounded tf32)
    float wreg[64];
    {
        const float* Wd = Whh + (size_t)dir * G4 * HH + (size_t)(nt * HH + j0 + g) * HH;
#pragma unroll
        for (int kt = 0; kt < 32; ++kt) {
            wreg[2 * kt]     = Wd[kt * 8 + t];
            wreg[2 * kt + 1] = Wd[kt * 8 + t + 4];
        }
    }

    const float* xWD = xW + (size_t)dir * BB * T * G4;
    float*       hD  = g_h + (size_t)dir * HH * BB;   // [j][b]
    const int eb = tid & 63, eu = tid >> 6;           // epilogue: (b, units eu, eu+4)
    float cst[2] = {0.f, 0.f};

    for (int s = 0; s < T; ++s) {
        const int tt = dir ? (T - 1 - s) : s;
        {   // stage xW: thread (b=eb, gate=eu) loads 8 unit values
            const float* src = &xWD[((size_t)eb * T + tt) * G4 + eu * HH + j0];
            float4 v0 = *(const float4*)src;
            float4 v1 = *(const float4*)(src + 4);
            float* d = &xw_sh[eb * 33 + eu * 8];
            d[0] = v0.x; d[1] = v0.y; d[2] = v0.z; d[3] = v0.w;
            d[4] = v1.x; d[5] = v1.y; d[6] = v1.z; d[7] = v1.w;
        }
        if (s > 0) {   // reload h (same [j][b] layout, padded rows)
            const float4* h4 = (const float4*)hD;
#pragma unroll
            for (int i = 0; i < 16; ++i) {
                int idx4 = tid + i * 256;
                int j = idx4 >> 4, b4 = (idx4 & 15) << 2;
                float4 v = __ldcg(h4 + idx4);
                *(float4*)&h_sh[j * LPAD + b4] = v;
            }
        }
        __syncthreads();

        float cf[2][4] = {{0.f, 0.f, 0.f, 0.f}, {0.f, 0.f, 0.f, 0.f}};
        if (s > 0) {
#pragma unroll
            for (int kt = 0; kt < 32; ++kt) {
                const float* hr0 = &h_sh[(kt * 8 + t) * LPAD];
                const float* hr1 = &h_sh[(kt * 8 + t + 4) * LPAD];
                uint32_t b0 = __float_as_uint(wreg[2 * kt]);
                uint32_t b1 = __float_as_uint(wreg[2 * kt + 1]);
#pragma unroll
                for (int p = 0; p < 2; ++p) {
                    int mb = mtp * 16 + p * 32;
                    uint32_t a0 = __float_as_uint(hr0[mb + g]);
                    uint32_t a1 = __float_as_uint(hr0[mb + g + 8]);
                    uint32_t a2 = __float_as_uint(hr1[mb + g]);
                    uint32_t a3 = __float_as_uint(hr1[mb + g + 8]);
                    asm volatile(
                        "mma.sync.aligned.m16n8k8.row.col.f32.tf32.tf32.f32 "
                        "{%0,%1,%2,%3}, {%4,%5,%6,%7}, {%8,%9}, {%0,%1,%2,%3};\n"
                        : "+f"(cf[p][0]), "+f"(cf[p][1]), "+f"(cf[p][2]), "+f"(cf[p][3])
                        : "r"(a0), "r"(a1), "r"(a2), "r"(a3), "r"(b0), "r"(b1));
                }
            }
        }
        // write P: col = gate*8 + unit_offset
#pragma unroll
        for (int p = 0; p < 2; ++p) {
            int mb = mtp * 16 + p * 32;
            int cc = nt * 8 + 2 * t;
            P_sh[(mb + g) * 33 + cc]     = cf[p][0];
            P_sh[(mb + g) * 33 + cc + 1] = cf[p][1];
            P_sh[(mb + g + 8) * 33 + cc]     = cf[p][2];
            P_sh[(mb + g + 8) * 33 + cc + 1] = cf[p][3];
        }
        __syncthreads();

        // epilogue: thread (eb, eu) handles units eu and eu+4
#pragma unroll
        for (int u = 0; u < 2; ++u) {
            int ju = eu + u * 4;
            const float* Pr = &P_sh[eb * 33];
            const float* Xr = &xw_sh[eb * 33];
            float pi = Pr[ju]      + Xr[ju];
            float pf = Pr[8 + ju]  + Xr[8 + ju];
            float pg = Pr[16 + ju] + Xr[16 + ju];
            float po = Pr[24 + ju] + Xr[24 + ju];
            float ig = sigmoidf_(pi);
            float fg = sigmoidf_(pf);
            float gg = tanhf(pg);
            float og = sigmoidf_(po);
            cst[u] = fg * cst[u] + ig * gg;
            float hh = og * tanhf(cst[u]);
            __stcg(&hD[(j0 + ju) * BB + eb], rtf(hh));
            out[((size_t)eb * T + tt) * H2 + dir * HH + j0 + ju] = hh;
        }
        if (s + 1 < T) grid_barrier(gridDim.x);
    }
}

// ---------------------------------------------------------------------------
__global__ void rowdot(const float* __restrict__ A, const float* __restrict__ w,
                       const float* __restrict__ bias, float* __restrict__ out, int rows)
{
    int gw = (blockIdx.x * blockDim.x + threadIdx.x) >> 5;
    int lane = threadIdx.x & 31;
    if (gw >= rows) return;
    const float* row = A + (size_t)gw * H2;
    float s = 0.f;
#pragma unroll
    for (int i = 0; i < 16; ++i) s += row[lane + i * 32] * w[lane + i * 32];
#pragma unroll
    for (int off = 16; off; off >>= 1) s += __shfl_xor_sync(0xffffffffu, s, off);
    if (lane == 0) out[gw] = s + (bias ? bias[0] : 0.f);
}

__global__ void __launch_bounds__(256)
attn_S(const float* __restrict__ c_out, const float* __restrict__ q_out,
       const float* __restrict__ sim_w, const float* __restrict__ sim_b,
       const float* __restrict__ cw, const float* __restrict__ qw,
       float* __restrict__ S)
{
    __shared__ float As[16][68];
    __shared__ float Bs[16][68];
    const int b = blockIdx.y, cc0 = blockIdx.x * 64;
    const float* A  = c_out + ((size_t)b * LC + cc0) * H2;
    const float* Bq = q_out + (size_t)b * LQ * H2;
    const float* wcq = sim_w + 2 * H2;
    const int tid = threadIdx.x;
    const int lr = tid >> 2, lk4 = (tid & 3) * 4;
    const int tx = tid & 15, ty = tid >> 4;
    float acc[4][4];
#pragma unroll
    for (int i = 0; i < 4; ++i)
#pragma unroll
        for (int j = 0; j < 4; ++j) acc[i][j] = 0.f;

    for (int k0 = 0; k0 < H2; k0 += 16) {
        float4 va = *(const float4*)&A[(size_t)lr * H2 + k0 + lk4];
        float4 wv = *(const float4*)&wcq[k0 + lk4];
        As[lk4 + 0][lr] = va.x * wv.x;
        As[lk4 + 1][lr] = va.y * wv.y;
        As[lk4 + 2][lr] = va.z * wv.z;
        As[lk4 + 3][lr] = va.w * wv.w;
        float4 vb = *(const float4*)&Bq[(size_t)lr * H2 + k0 + lk4];
        Bs[lk4 + 0][lr] = vb.x;
        Bs[lk4 + 1][lr] = vb.y;
        Bs[lk4 + 2][lr] = vb.z;
        Bs[lk4 + 3][lr] = vb.w;
        __syncthreads();
#pragma unroll
        for (int k = 0; k < 16; ++k) {
            float4 av = *(const float4*)&As[k][ty * 4];
            float4 bv = *(const float4*)&Bs[k][tx * 4];
            float am[4] = {av.x, av.y, av.z, av.w};
            float bn[4] = {bv.x, bv.y, bv.z, bv.w};
#pragma unroll
            for (int i = 0; i < 4; ++i)
#pragma unroll
                for (int j = 0; j < 4; ++j) acc[i][j] += am[i] * bn[j];
        }
        __syncthreads();
    }
    float sb = sim_b[0];
#pragma unroll
    for (int i = 0; i < 4; ++i) {
        int cc = cc0 + ty * 4 + i;
        float cwv = cw[b * LC + cc];
#pragma unroll
        for (int j = 0; j < 4; ++j) {
            int qq = tx * 4 + j;
            S[((size_t)b * LC + cc) * LQ + qq] = acc[i][j] + cwv + qw[b * LQ + qq] + sb;
        }
    }
}

__global__ void softmax64(float* __restrict__ S, float* __restrict__ smax, int rows)
{
    int gw = (blockIdx.x * blockDim.x + threadIdx.x) >> 5;
    int lane = threadIdx.x & 31;
    if (gw >= rows) return;
    float* row = S + (size_t)gw * LQ;
    float v0 = row[lane], v1 = row[lane + 32];
    float m = fmaxf(v0, v1);
#pragma unroll
    for (int off = 16; off; off >>= 1) m = fmaxf(m, __shfl_xor_sync(0xffffffffu, m, off));
    float e0 = expf(v0 - m), e1 = expf(v1 - m);
    float s = e0 + e1;
#pragma unroll
    for (int off = 16; off; off >>= 1) s += __shfl_xor_sync(0xffffffffu, s, off);
    float inv = 1.f / s;
    row[lane] = e0 * inv;
    row[lane + 32] = e1 * inv;
    if (lane == 0) smax[gw] = m;
}

__global__ void softmax512(const float* __restrict__ in, float* __restrict__ outv)
{
    __shared__ float red[16];
    int b = blockIdx.x, tid = threadIdx.x;
    float v = in[(size_t)b * LC + tid];
    float m = v;
#pragma unroll
    for (int off = 16; off; off >>= 1) m = fmaxf(m, __shfl_xor_sync(0xffffffffu, m, off));
    if ((tid & 31) == 0) red[tid >> 5] = m;
    __syncthreads();
    if (tid == 0) {
        float x = red[0];
        for (int i = 1; i < 16; ++i) x = fmaxf(x, red[i]);
        red[0] = x;
    }
    __syncthreads();
    m = red[0];
    __syncthreads();
    float e = expf(v - m);
    float s = e;
#pragma unroll
    for (int off = 16; off; off >>= 1) s += __shfl_xor_sync(0xffffffffu, s, off);
    if ((tid & 31) == 0) red[tid >> 5] = s;
    __syncthreads();
    if (tid == 0) {
        float x = 0.f;
        for (int i = 0; i < 16; ++i) x += red[i];
        red[0] = x;
    }
    __syncthreads();
    outv[(size_t)b * LC + tid] = e / red[0];
}

__global__ void __launch_bounds__(256)
attn_c2q(const float* __restrict__ a, const float* __restrict__ q_out,
         float* __restrict__ c2q)
{
    __shared__ float As[16][68];
    __shared__ float Bs[16][68];
    const int b = blockIdx.z, cc0 = blockIdx.y * 64, h0 = blockIdx.x * 64;
    const float* A = a + ((size_t)b * LC + cc0) * LQ;
    const float* B = q_out + (size_t)b * LQ * H2;
    const int tid = threadIdx.x;
    const int lr = tid >> 2, lk4 = (tid & 3) * 4;
    const int bk = tid >> 4, bn4 = (tid & 15) * 4;
    const int tx = tid & 15, ty = tid >> 4;
    float acc[4][4];
#pragma unroll
    for (int i = 0; i < 4; ++i)
#pragma unroll
        for (int j = 0; j < 4; ++j) acc[i][j] = 0.f;

    for (int k0 = 0; k0 < LQ; k0 += 16) {
        float4 va = *(const float4*)&A[(size_t)lr * LQ + k0 + lk4];
        As[lk4 + 0][lr] = va.x;
        As[lk4 + 1][lr] = va.y;
        As[lk4 + 2][lr] = va.z;
        As[lk4 + 3][lr] = va.w;
        float4 vb = *(const float4*)&B[(size_t)(k0 + bk) * H2 + h0 + bn4];
        *(float4*)&Bs[bk][bn4] = vb;
        __syncthreads();
#pragma unroll
        for (int k = 0; k < 16; ++k) {
            float4 av = *(const float4*)&As[k][ty * 4];
            float4 bv = *(const float4*)&Bs[k][tx * 4];
            float am[4] = {av.x, av.y, av.z, av.w};
            float bn[4] = {bv.x, bv.y, bv.z, bv.w};
#pragma unroll
            for (int i = 0; i < 4; ++i)
#pragma unroll
                for (int j = 0; j < 4; ++j) acc[i][j] += am[i] * bn[j];
        }
        __syncthreads();
    }
#pragma unroll
    for (int i = 0; i < 4; ++i)
#pragma unroll
        for (int j = 0; j < 4; ++j)
            c2q[((size_t)b * LC + cc0 + ty * 4 + i) * H2 + h0 + tx * 4 + j] = acc[i][j];
}

__global__ void attn_q2c(const float* __restrict__ batt, const float* __restrict__ c_out,
                         float* __restrict__ q2c)
{
    int b = blockIdx.y;
    int h = blockIdx.x * 128 + threadIdx.x;
    const float* C = c_out + (size_t)b * LC * H2;
    const float* w = batt + (size_t)b * LC;
    float acc = 0.f;
    for (int cc = 0; cc < LC; ++cc) acc += w[cc] * C[(size_t)cc * H2 + h];
    q2c[(size_t)b * H2 + h] = acc;
}

__global__ void build_G(const float* __restrict__ c_out, const float* __restrict__ c2q,
                        const float* __restrict__ q2c, float* __restrict__ G)
{
    size_t i = (size_t)blockIdx.x * blockDim.x + threadIdx.x;
    const size_t total = (size_t)BB * LC * (H2 / 4);
    if (i >= total) return;
    int h4 = (int)(i % (H2 / 4));
    size_t r = i / (H2 / 4);
    int b = (int)(r / LC);
    float4 co = ((const float4*)c_out)[r * (H2 / 4) + h4];
    float4 cq = ((const float4*)c2q)[r * (H2 / 4) + h4];
    float4 q2 = ((const float4*)q2c)[(size_t)b * (H2 / 4) + h4];
    float4* Gr = (float4*)(G + r * H8);
    Gr[h4] = make_float4(rtf(co.x), rtf(co.y), rtf(co.z), rtf(co.w));
    Gr[(H2 / 4) + h4] = make_float4(rtf(cq.x), rtf(cq.y), rtf(cq.z), rtf(cq.w));
    Gr[2 * (H2 / 4) + h4] = make_float4(rtf(co.x * cq.x), rtf(co.y * cq.y),
                                        rtf(co.z * cq.z), rtf(co.w * cq.w));
    Gr[3 * (H2 / 4) + h4] = make_float4(rtf(co.x * q2.x), rtf(co.y * q2.y),
                                        rtf(co.z * q2.z), rtf(co.w * q2.w));
}

// ---------------------------------------------------------------------------
extern "C" void kernel_launch(void* const* d_in, const int* in_sizes, int n_in,
                              void* d_out, int out_size)
{
    const int*   q       = (const int*)  d_in[0];
    const int*   c       = (const int*)  d_in[1];
    const float* emb     = (const float*)d_in[2];
    const float* Wih_q   = (const float*)d_in[3];
    const float* Whh_q   = (const float*)d_in[4];
    const float* b_q     = (const float*)d_in[5];
    const float* Wih_c   = (const float*)d_in[6];
    const float* Whh_c   = (const float*)d_in[7];
    const float* b_c     = (const float*)d_in[8];
    const float* Wih_m   = (const float*)d_in[9];
    const float* Whh_m   = (const float*)d_in[10];
    const float* b_m     = (const float*)d_in[11];
    const float* sim_w   = (const float*)d_in[12];
    const float* sim_b   = (const float*)d_in[13];
    const float* start_w = (const float*)d_in[14];
    const float* start_b = (const float*)d_in[15];
    const float* end_w   = (const float*)d_in[16];
    const float* end_b   = (const float*)d_in[17];
    float* out = (float*)d_out;

    float *qemb, *cemb, *xw, *qout, *cout, *S, *smax, *batt, *cw, *qw, *c2q, *q2c, *G, *M, *wcvt, *whh;
    cudaGetSymbolAddress((void**)&qemb, g_qemb);
    cudaGetSymbolAddress((void**)&cemb, g_cemb);
    cudaGetSymbolAddress((void**)&xw,   g_xw);
    cudaGetSymbolAddress((void**)&qout, g_qout);
    cudaGetSymbolAddress((void**)&cout, g_cout);
    cudaGetSymbolAddress((void**)&S,    g_S);
    cudaGetSymbolAddress((void**)&smax, g_smax);
    cudaGetSymbolAddress((void**)&batt, g_batt);
    cudaGetSymbolAddress((void**)&cw,   g_cw);
    cudaGetSymbolAddress((void**)&qw,   g_qw);
    cudaGetSymbolAddress((void**)&c2q,  g_c2q);
    cudaGetSymbolAddress((void**)&q2c,  g_q2c);
    cudaGetSymbolAddress((void**)&G,    g_G);
    cudaGetSymbolAddress((void**)&M,    g_M);
    cudaGetSymbolAddress((void**)&wcvt, g_wcvt);
    cudaGetSymbolAddress((void**)&whh,  g_whh);

    cudaFuncSetAttribute(lstm_scan, cudaFuncAttributeMaxDynamicSharedMemorySize, SCAN_SMEM);
    cudaFuncSetAttribute(gemm_tf32, cudaFuncAttributeMaxDynamicSharedMemorySize, GEMM_SMEM);

    gather_emb<<<(BB * LQ * EE + 255) / 256, 256>>>(q, emb, qemb, BB * LQ * EE);
    gather_emb<<<(BB * LC * EE + 255) / 256, 256>>>(c, emb, cemb, BB * LC * EE);

    // q BiLSTM
    cvt_tf32<<<(2 * G4 * EE + 255) / 256, 256>>>(Wih_q, wcvt, 2 * G4 * EE);
    cvt_tf32<<<(2 * G4 * HH + 255) / 256, 256>>>(Whh_q, whh, 2 * G4 * HH);
    for (int d = 0; d < 2; ++d)
        gemm_tf32<<<dim3(G4 / 128, (BB * LQ) / 128), 128, GEMM_SMEM>>>(
            qemb, wcvt + (size_t)d * G4 * EE, b_q + (size_t)d * G4,
            xw + (size_t)d * BB * LQ * G4, BB * LQ, G4, EE);
    lstm_scan<<<64, 256, SCAN_SMEM>>>(xw, whh, qout, LQ);

    // c BiLSTM
    cvt_tf32<<<(2 * G4 * EE + 255) / 256, 256>>>(Wih_c, wcvt, 2 * G4 * EE);
    cvt_tf32<<<(2 * G4 * HH + 255) / 256, 256>>>(Whh_c, whh, 2 * G4 * HH);
    for (int d = 0; d < 2; ++d)
        gemm_tf32<<<dim3(G4 / 128, (BB * LC) / 128), 128, GEMM_SMEM>>>(
            cemb, wcvt + (size_t)d * G4 * EE, b_c + (size_t)d * G4,
            xw + (size_t)d * BB * LC * G4, BB * LC, G4, EE);
    lstm_scan<<<64, 256, SCAN_SMEM>>>(xw, whh, cout, LC);

    // attention
    rowdot<<<(BB * LC) / 8, 256>>>(cout, sim_w, nullptr, cw, BB * LC);
    rowdot<<<(BB * LQ) / 8, 256>>>(qout, sim_w + H2, nullptr, qw, BB * LQ);
    attn_S<<<dim3(LC / 64, BB), 256>>>(cout, qout, sim_w, sim_b, cw, qw, S);
    softmax64<<<(BB * LC) / 8, 256>>>(S, smax, BB * LC);
    softmax512<<<BB, 512>>>(smax, batt);
    attn_c2q<<<dim3(H2 / 64, LC / 64, BB), 256>>>(S, qout, c2q);
    attn_q2c<<<dim3(H2 / 128, BB), 128>>>(batt, cout, q2c);
    build_G<<<(int)(((size_t)BB * LC * (H2 / 4) + 255) / 256), 256>>>(cout, c2q, q2c, G);

    // modeling BiLSTM
    cvt_tf32<<<(2 * G4 * H8 + 255) / 256, 256>>>(Wih_m, wcvt, 2 * G4 * H8);
    cvt_tf32<<<(2 * G4 * HH + 255) / 256, 256>>>(Whh_m, whh, 2 * G4 * HH);
    for (int d = 0; d < 2; ++d)
        gemm_tf32<<<dim3(G4 / 128, (BB * LC) / 128), 128, GEMM_SMEM>>>(
            G, wcvt + (size_t)d * G4 * H8, b_m + (size_t)d * G4,
            xw + (size_t)d * BB * LC * G4, BB * LC, G4, H8);
    lstm_scan<<<64, 256, SCAN_SMEM>>>(xw, whh, M, LC);

    rowdot<<<(BB * LC) / 8, 256>>>(M, start_w, start_b, out, BB * LC);
    rowdot<<<(BB * LC) / 8, 256>>>(M, end_w, end_b, out + (size_t)BB * LC, BB * LC);
}

// round 13
// speedup vs baseline: 1.3069x; 1.0637x over previous
#include <cuda_runtime.h>
#include <cuda_bf16.h>
#include <math.h>
#include <stdint.h>

#define EE   300
#define HH   256
#define G4   1024
#define H2   512
#define H8   2048
#define BB   64
#define LQ   64
#define LC   512

__device__ float g_qemb[(size_t)BB * LQ * EE];
__device__ float g_cemb[(size_t)BB * LC * EE];
__device__ float g_xw  [(size_t)2 * BB * LC * G4];
__device__ float g_xwq [(size_t)2 * BB * LQ * G4];
__device__ float g_qout[(size_t)BB * LQ * H2];
__device__ float g_cout[(size_t)BB * LC * H2];
__device__ float g_S   [(size_t)BB * LC * LQ];
__device__ float g_smax[(size_t)BB * LC];
__device__ float g_batt[(size_t)BB * LC];
__device__ float g_cw  [(size_t)BB * LC];
__device__ float g_qw  [(size_t)BB * LQ];
__device__ float g_c2q [(size_t)BB * LC * H2];
__device__ float g_q2c [(size_t)BB * H2];
__device__ float g_G   [(size_t)BB * LC * H8];
__device__ float g_M   [(size_t)BB * LC * H2];
__device__ float g_h   [(size_t)4 * HH * BB];        // [group][dir][j][b]
__device__ float g_wcvt[(size_t)2 * G4 * H8];
__device__ float g_whh [(size_t)4 * G4 * HH];        // [group][dir]...
__device__ unsigned g_bar_cnt2[2] = {0, 0};
__device__ unsigned g_bar_gen2[2] = {0, 0};

__device__ __forceinline__ float sigmoidf_(float x) { return 1.f / (1.f + expf(-x)); }

__device__ __forceinline__ uint32_t f2tf32(float x)
{
    uint32_t r;
    asm("cvt.rna.tf32.f32 %0, %1;" : "=r"(r) : "f"(x));
    return r;
}
__device__ __forceinline__ float rtf(float x) { return __uint_as_float(f2tf32(x)); }

// Fence-lite grouped grid barrier: proxy-thread release/acquire.
__device__ __forceinline__ void grid_barrier_g(int grp, unsigned nb)
{
    __syncthreads();
    if (threadIdx.x == 0) {
        asm volatile("fence.acq_rel.gpu;" ::: "memory");     // release (cumulative)
        unsigned g = *(volatile unsigned*)&g_bar_gen2[grp];
        if (atomicAdd(&g_bar_cnt2[grp], 1u) == nb - 1u) {
            g_bar_cnt2[grp] = 0;
            __threadfence();
            atomicAdd(&g_bar_gen2[grp], 1u);
        } else {
            while (*(volatile unsigned*)&g_bar_gen2[grp] == g) { }
        }
        asm volatile("fence.acq_rel.gpu;" ::: "memory");     // acquire (cumulative)
    }
    __syncthreads();
}

__device__ __forceinline__ void cp16(uint32_t dst, const void* src)
{
    asm volatile("cp.async.cg.shared.global [%0], [%1], 16;" :: "r"(dst), "l"(src));
}
__device__ __forceinline__ uint32_t smem_u32(const void* p)
{
    uint32_t a;
    asm("{ .reg .u64 t; cvta.to.shared.u64 t, %1; cvt.u32.u64 %0, t; }" : "=r"(a) : "l"(p));
    return a;
}

// ---------------------------------------------------------------------------
__global__ void gather_emb(const int* __restrict__ tok, const float* __restrict__ emb,
                           float* __restrict__ out, int total)
{
    int i = blockIdx.x * blockDim.x + threadIdx.x;
    if (i >= total) return;
    int row = i / EE;
    int e   = i - row * EE;
    out[i] = rtf(emb[(size_t)tok[row] * EE + e]);
}

__global__ void cvt_tf32(const float* __restrict__ in, float* __restrict__ out, int n)
{
    int i = blockIdx.x * blockDim.x + threadIdx.x;
    if (i < n) out[i] = rtf(in[i]);
}

// ---------------------------------------------------------------------------
// tf32 mma.sync GEMM v2 (best measured ~94 TF/s): C=A[M,K]*B[N,K]^T + bias.
// CTA 128x128, 4 warps, warp tile 64x64, BK=32, cp.async 2-stage.
// ---------------------------------------------------------------------------
#define SROW 36
#define STILE (128 * SROW)
#define GEMM_SMEM (4 * STILE * (int)sizeof(float))   // 73728 B

__device__ __forceinline__ void fill_tile(uint32_t sA, uint32_t sB,
                                          const float* __restrict__ A,
                                          const float* __restrict__ B,
                                          int bm, int bn, int K, int k0, int tid)
{
#pragma unroll
    for (int i = 0; i < 8; ++i) {
        int idx = tid + i * 128;
        int row = idx >> 3, c4 = idx & 7;
        int k = k0 + c4 * 4;
        uint32_t da = sA + (row * SROW + c4 * 4) * 4;
        uint32_t db = sB + (row * SROW + c4 * 4) * 4;
        if (k + 4 <= K) {
            cp16(da, &A[(size_t)(bm + row) * K + k]);
            cp16(db, &B[(size_t)(bn + row) * K + k]);
        } else {
            asm volatile("st.shared.v4.b32 [%0], {%1,%1,%1,%1};" :: "r"(da), "r"(0) : "memory");
            asm volatile("st.shared.v4.b32 [%0], {%1,%1,%1,%1};" :: "r"(db), "r"(0) : "memory");
        }
    }
}

__global__ void __launch_bounds__(128)
gemm_tf32(const float* __restrict__ A, const float* __restrict__ B,
          const float* __restrict__ bias, float* __restrict__ C,
          int M, int N, int K)
{
    extern __shared__ float sh[];
    const int tid  = threadIdx.x;
    const int lane = tid & 31;
    const int warp = tid >> 5;
    const int g = lane >> 2, t = lane & 3;
    const int m0 = (warp & 1) * 64;
    const int n0 = (warp >> 1) * 64;
    const int bm = blockIdx.y * 128;
    const int bn = blockIdx.x * 128;
    const uint32_t sb = smem_u32(sh);

    float acc[4][8][4];
#pragma unroll
    for (int mi = 0; mi < 4; ++mi)
#pragma unroll
        for (int ni = 0; ni < 8; ++ni)
#pragma unroll
            for (int k = 0; k < 4; ++k) acc[mi][ni][k] = 0.f;

    const int nk = (K + 31) >> 5;
    const uint32_t stage_b = 2 * STILE * 4;

    fill_tile(sb, sb + STILE * 4, A, B, bm, bn, K, 0, tid);
    asm volatile("cp.async.commit_group;" ::: "memory");

    int buf = 0;
    for (int kt = 0; kt < nk; ++kt) {
        if (kt + 1 < nk) {
            fill_tile(sb + (buf ^ 1) * stage_b, sb + (buf ^ 1) * stage_b + STILE * 4,
                      A, B, bm, bn, K, (kt + 1) * 32, tid);
            asm volatile("cp.async.commit_group;" ::: "memory");
            asm volatile("cp.async.wait_group 1;" ::: "memory");
        } else {
            asm volatile("cp.async.wait_group 0;" ::: "memory");
        }
        __syncthreads();

        const float* Ab = sh + buf * 2 * STILE;
        const float* Bb = Ab + STILE;
#pragma unroll
        for (int kk = 0; kk < 32; kk += 8) {
            uint32_t af[4][4];
#pragma unroll
            for (int mi = 0; mi < 4; ++mi) {
                const float* ap = Ab + (m0 + mi * 16) * SROW + kk;
                af[mi][0] = __float_as_uint(ap[g * SROW + t]);
                af[mi][1] = __float_as_uint(ap[(g + 8) * SROW + t]);
                af[mi][2] = __float_as_uint(ap[g * SROW + t + 4]);
                af[mi][3] = __float_as_uint(ap[(g + 8) * SROW + t + 4]);
            }
            uint32_t bf[8][2];
#pragma unroll
            for (int ni = 0; ni < 8; ++ni) {
                const float* bp = Bb + (n0 + ni * 8) * SROW + kk;
                bf[ni][0] = __float_as_uint(bp[g * SROW + t]);
                bf[ni][1] = __float_as_uint(bp[g * SROW + t + 4]);
            }
#pragma unroll
            for (int mi = 0; mi < 4; ++mi)
#pragma unroll
                for (int ni = 0; ni < 8; ++ni)
                    asm volatile(
                        "mma.sync.aligned.m16n8k8.row.col.f32.tf32.tf32.f32 "
                        "{%0,%1,%2,%3}, {%4,%5,%6,%7}, {%8,%9}, {%0,%1,%2,%3};\n"
                        : "+f"(acc[mi][ni][0]), "+f"(acc[mi][ni][1]),
                          "+f"(acc[mi][ni][2]), "+f"(acc[mi][ni][3])
                        : "r"(af[mi][0]), "r"(af[mi][1]), "r"(af[mi][2]), "r"(af[mi][3]),
                          "r"(bf[ni][0]), "r"(bf[ni][1]));
        }
        __syncthreads();
        buf ^= 1;
    }

#pragma unroll
    for (int mi = 0; mi < 4; ++mi) {
#pragma unroll
        for (int ni = 0; ni < 8; ++ni) {
            int row0 = bm + m0 + mi * 16 + g;
            int col  = bn + n0 + ni * 8 + t * 2;
            float2 bv = make_float2(0.f, 0.f);
            if (bias) bv = *(const float2*)&bias[col];
            *(float2*)&C[(size_t)row0 * N + col] =
                make_float2(acc[mi][ni][0] + bv.x, acc[mi][ni][1] + bv.y);
            *(float2*)&C[(size_t)(row0 + 8) * N + col] =
                make_float2(acc[mi][ni][2] + bv.x, acc[mi][ni][3] + bv.y);
        }
    }
}

// ---------------------------------------------------------------------------
// BiLSTM scan, tensor-core recurrence, TWO independent groups per launch.
// Group g (64 blocks) scans (xW_g, Whh_g) -> out_g over T_g steps; groups
// barrier independently. Block = (dir, 8-unit chunk); 256 threads.
// ---------------------------------------------------------------------------
#define LPAD 72
#define SC_H   (HH * LPAD)
#define SC_XW  (SC_H + BB * 33)
#define SC_TOT (SC_XW + BB * 33)
#define SCAN_SMEM (SC_TOT * (int)sizeof(float))   // 90624 B

__global__ void __launch_bounds__(256)
lstm_scan2(const float* __restrict__ xW0, const float* __restrict__ Whh0,
           float* __restrict__ out0, int T0,
           const float* __restrict__ xW1, const float* __restrict__ Whh1,
           float* __restrict__ out1, int T1)
{
    extern __shared__ float sh[];
    float* h_sh  = sh;                 // [256][72]
    float* xw_sh = sh + SC_H;          // [64][33]
    float* P_sh  = sh + SC_XW;         // [64][33]

    const int tid  = threadIdx.x;
    const int lane = tid & 31;
    const int warp = tid >> 5;
    const int g = lane >> 2, t = lane & 3;
    const int nt  = warp >> 1;
    const int mtp = warp & 1;
    const int grp = blockIdx.x >> 6;
    const int bid = blockIdx.x & 63;
    const int dir = bid >> 5;
    const int j0  = (bid & 31) * 8;

    const float* xWall = grp ? xW1 : xW0;
    const float* Whh   = grp ? Whh1 : Whh0;
    float*       outp  = grp ? out1 : out0;
    const int    T     = grp ? T1 : T0;

    float wreg[64];
    {
        const float* Wd = Whh + (size_t)dir * G4 * HH + (size_t)(nt * HH + j0 + g) * HH;
#pragma unroll
        for (int kt = 0; kt < 32; ++kt) {
            wreg[2 * kt]     = Wd[kt * 8 + t];
            wreg[2 * kt + 1] = Wd[kt * 8 + t + 4];
        }
    }

    const float* xWD = xWall + (size_t)dir * BB * T * G4;
    float*       hD  = g_h + (size_t)(grp * 2 + dir) * HH * BB;
    const int eb = tid & 63, eu = tid >> 6;
    float cst[2] = {0.f, 0.f};

    for (int s = 0; s < T; ++s) {
        const int tt = dir ? (T - 1 - s) : s;
        {
            const float* src = &xWD[((size_t)eb * T + tt) * G4 + eu * HH + j0];
            float4 v0 = *(const float4*)src;
            float4 v1 = *(const float4*)(src + 4);
            float* d = &xw_sh[eb * 33 + eu * 8];
            d[0] = v0.x; d[1] = v0.y; d[2] = v0.z; d[3] = v0.w;
            d[4] = v1.x; d[5] = v1.y; d[6] = v1.z; d[7] = v1.w;
        }
        if (s > 0) {
            const float4* h4 = (const float4*)hD;
#pragma unroll
            for (int i = 0; i < 16; ++i) {
                int idx4 = tid + i * 256;
                int j = idx4 >> 4, b4 = (idx4 & 15) << 2;
                float4 v = __ldcg(h4 + idx4);
                *(float4*)&h_sh[j * LPAD + b4] = v;
            }
        }
        __syncthreads();

        float cf[2][4] = {{0.f, 0.f, 0.f, 0.f}, {0.f, 0.f, 0.f, 0.f}};
        if (s > 0) {
#pragma unroll
            for (int kt = 0; kt < 32; ++kt) {
                const float* hr0 = &h_sh[(kt * 8 + t) * LPAD];
                const float* hr1 = &h_sh[(kt * 8 + t + 4) * LPAD];
                uint32_t b0 = __float_as_uint(wreg[2 * kt]);
                uint32_t b1 = __float_as_uint(wreg[2 * kt + 1]);
#pragma unroll
                for (int p = 0; p < 2; ++p) {
                    int mb = mtp * 16 + p * 32;
                    uint32_t a0 = __float_as_uint(hr0[mb + g]);
                    uint32_t a1 = __float_as_uint(hr0[mb + g + 8]);
                    uint32_t a2 = __float_as_uint(hr1[mb + g]);
                    uint32_t a3 = __float_as_uint(hr1[mb + g + 8]);
                    asm volatile(
                        "mma.sync.aligned.m16n8k8.row.col.f32.tf32.tf32.f32 "
                        "{%0,%1,%2,%3}, {%4,%5,%6,%7}, {%8,%9}, {%0,%1,%2,%3};\n"
                        : "+f"(cf[p][0]), "+f"(cf[p][1]), "+f"(cf[p][2]), "+f"(cf[p][3])
                        : "r"(a0), "r"(a1), "r"(a2), "r"(a3), "r"(b0), "r"(b1));
                }
            }
        }
#pragma unroll
        for (int p = 0; p < 2; ++p) {
            int mb = mtp * 16 + p * 32;
            int cc = nt * 8 + 2 * t;
            P_sh[(mb + g) * 33 + cc]     = cf[p][0];
            P_sh[(mb + g) * 33 + cc + 1] = cf[p][1];
            P_sh[(mb + g + 8) * 33 + cc]     = cf[p][2];
            P_sh[(mb + g + 8) * 33 + cc + 1] = cf[p][3];
        }
        __syncthreads();

#pragma unroll
        for (int u = 0; u < 2; ++u) {
            int ju = eu + u * 4;
            const float* Pr = &P_sh[eb * 33];
            const float* Xr = &xw_sh[eb * 33];
            float pi = Pr[ju]      + Xr[ju];
            float pf = Pr[8 + ju]  + Xr[8 + ju];
            float pg = Pr[16 + ju] + Xr[16 + ju];
            float po = Pr[24 + ju] + Xr[24 + ju];
            float ig = sigmoidf_(pi);
            float fg = sigmoidf_(pf);
            float gg = tanhf(pg);
            float og = sigmoidf_(po);
            cst[u] = fg * cst[u] + ig * gg;
            float hh = og * tanhf(cst[u]);
            __stcg(&hD[(j0 + ju) * BB + eb], rtf(hh));
            outp[((size_t)eb * T + tt) * H2 + dir * HH + j0 + ju] = hh;
        }
        if (s + 1 < T) grid_barrier_g(grp, 64);
    }
}

// ---------------------------------------------------------------------------
__global__ void rowdot(const float* __restrict__ A, const float* __restrict__ w,
                       const float* __restrict__ bias, float* __restrict__ out, int rows)
{
    int gw = (blockIdx.x * blockDim.x + threadIdx.x) >> 5;
    int lane = threadIdx.x & 31;
    if (gw >= rows) return;
    const float* row = A + (size_t)gw * H2;
    float s = 0.f;
#pragma unroll
    for (int i = 0; i < 16; ++i) s += row[lane + i * 32] * w[lane + i * 32];
#pragma unroll
    for (int off = 16; off; off >>= 1) s += __shfl_xor_sync(0xffffffffu, s, off);
    if (lane == 0) out[gw] = s + (bias ? bias[0] : 0.f);
}

__global__ void __launch_bounds__(256)
attn_S(const float* __restrict__ c_out, const float* __restrict__ q_out,
       const float* __restrict__ sim_w, const float* __restrict__ sim_b,
       const float* __restrict__ cw, const float* __restrict__ qw,
       float* __restrict__ S)
{
    __shared__ float As[16][68];
    __shared__ float Bs[16][68];
    const int b = blockIdx.y, cc0 = blockIdx.x * 64;
    const float* A  = c_out + ((size_t)b * LC + cc0) * H2;
    const float* Bq = q_out + (size_t)b * LQ * H2;
    const float* wcq = sim_w + 2 * H2;
    const int tid = threadIdx.x;
    const int lr = tid >> 2, lk4 = (tid & 3) * 4;
    const int tx = tid & 15, ty = tid >> 4;
    float acc[4][4];
#pragma unroll
    for (int i = 0; i < 4; ++i)
#pragma unroll
        for (int j = 0; j < 4; ++j) acc[i][j] = 0.f;

    for (int k0 = 0; k0 < H2; k0 += 16) {
        float4 va = *(const float4*)&A[(size_t)lr * H2 + k0 + lk4];
        float4 wv = *(const float4*)&wcq[k0 + lk4];
        As[lk4 + 0][lr] = va.x * wv.x;
        As[lk4 + 1][lr] = va.y * wv.y;
        As[lk4 + 2][lr] = va.z * wv.z;
        As[lk4 + 3][lr] = va.w * wv.w;
        float4 vb = *(const float4*)&Bq[(size_t)lr * H2 + k0 + lk4];
        Bs[lk4 + 0][lr] = vb.x;
        Bs[lk4 + 1][lr] = vb.y;
        Bs[lk4 + 2][lr] = vb.z;
        Bs[lk4 + 3][lr] = vb.w;
        __syncthreads();
#pragma unroll
        for (int k = 0; k < 16; ++k) {
            float4 av = *(const float4*)&As[k][ty * 4];
            float4 bv = *(const float4*)&Bs[k][tx * 4];
            float am[4] = {av.x, av.y, av.z, av.w};
            float bn[4] = {bv.x, bv.y, bv.z, bv.w};
#pragma unroll
            for (int i = 0; i < 4; ++i)
#pragma unroll
                for (int j = 0; j < 4; ++j) acc[i][j] += am[i] * bn[j];
        }
        __syncthreads();
    }
    float sb = sim_b[0];
#pragma unroll
    for (int i = 0; i < 4; ++i) {
        int cc = cc0 + ty * 4 + i;
        float cwv = cw[b * LC + cc];
#pragma unroll
        for (int j = 0; j < 4; ++j) {
            int qq = tx * 4 + j;
            S[((size_t)b * LC + cc) * LQ + qq] = acc[i][j] + cwv + qw[b * LQ + qq] + sb;
        }
    }
}

__global__ void softmax64(float* __restrict__ S, float* __restrict__ smax, int rows)
{
    int gw = (blockIdx.x * blockDim.x + threadIdx.x) >> 5;
    int lane = threadIdx.x & 31;
    if (gw >= rows) return;
    float* row = S + (size_t)gw * LQ;
    float v0 = row[lane], v1 = row[lane + 32];
    float m = fmaxf(v0, v1);
#pragma unroll
    for (int off = 16; off; off >>= 1) m = fmaxf(m, __shfl_xor_sync(0xffffffffu, m, off));
    float e0 = expf(v0 - m), e1 = expf(v1 - m);
    float s = e0 + e1;
#pragma unroll
    for (int off = 16; off; off >>= 1) s += __shfl_xor_sync(0xffffffffu, s, off);
    float inv = 1.f / s;
    row[lane] = e0 * inv;
    row[lane + 32] = e1 * inv;
    if (lane == 0) smax[gw] = m;
}

__global__ void softmax512(const float* __restrict__ in, float* __restrict__ outv)
{
    __shared__ float red[16];
    int b = blockIdx.x, tid = threadIdx.x;
    float v = in[(size_t)b * LC + tid];
    float m = v;
#pragma unroll
    for (int off = 16; off; off >>= 1) m = fmaxf(m, __shfl_xor_sync(0xffffffffu, m, off));
    if ((tid & 31) == 0) red[tid >> 5] = m;
    __syncthreads();
    if (tid == 0) {
        float x = red[0];
        for (int i = 1; i < 16; ++i) x = fmaxf(x, red[i]);
        red[0] = x;
    }
    __syncthreads();
    m = red[0];
    __syncthreads();
    float e = expf(v - m);
    float s = e;
#pragma unroll
    for (int off = 16; off; off >>= 1) s += __shfl_xor_sync(0xffffffffu, s, off);
    if ((tid & 31) == 0) red[tid >> 5] = s;
    __syncthreads();
    if (tid == 0) {
        float x = 0.f;
        for (int i = 0; i < 16; ++i) x += red[i];
        red[0] = x;
    }
    __syncthreads();
    outv[(size_t)b * LC + tid] = e / red[0];
}

__global__ void __launch_bounds__(256)
attn_c2q(const float* __restrict__ a, const float* __restrict__ q_out,
         float* __restrict__ c2q)
{
    __shared__ float As[16][68];
    __shared__ float Bs[16][68];
    const int b = blockIdx.z, cc0 = blockIdx.y * 64, h0 = blockIdx.x * 64;
    const float* A = a + ((size_t)b * LC + cc0) * LQ;
    const float* B = q_out + (size_t)b * LQ * H2;
    const int tid = threadIdx.x;
    const int lr = tid >> 2, lk4 = (tid & 3) * 4;
    const int bk = tid >> 4, bn4 = (tid & 15) * 4;
    const int tx = tid & 15, ty = tid >> 4;
    float acc[4][4];
#pragma unroll
    for (int i = 0; i < 4; ++i)
#pragma unroll
        for (int j = 0; j < 4; ++j) acc[i][j] = 0.f;

    for (int k0 = 0; k0 < LQ; k0 += 16) {
        float4 va = *(const float4*)&A[(size_t)lr * LQ + k0 + lk4];
        As[lk4 + 0][lr] = va.x;
        As[lk4 + 1][lr] = va.y;
        As[lk4 + 2][lr] = va.z;
        As[lk4 + 3][lr] = va.w;
        float4 vb = *(const float4*)&B[(size_t)(k0 + bk) * H2 + h0 + bn4];
        *(float4*)&Bs[bk][bn4] = vb;
        __syncthreads();
#pragma unroll
        for (int k = 0; k < 16; ++k) {
            float4 av = *(const float4*)&As[k][ty * 4];
            float4 bv = *(const float4*)&Bs[k][tx * 4];
            float am[4] = {av.x, av.y, av.z, av.w};
            float bn[4] = {bv.x, bv.y, bv.z, bv.w};
#pragma unroll
            for (int i = 0; i < 4; ++i)
#pragma unroll
                for (int j = 0; j < 4; ++j) acc[i][j] += am[i] * bn[j];
        }
        __syncthreads();
    }
#pragma unroll
    for (int i = 0; i < 4; ++i)
#pragma unroll
        for (int j = 0; j < 4; ++j)
            c2q[((size_t)b * LC + cc0 + ty * 4 + i) * H2 + h0 + tx * 4 + j] = acc[i][j];
}

__global__ void attn_q2c(const float* __restrict__ batt, const float* __restrict__ c_out,
                         float* __restrict__ q2c)
{
    int b = blockIdx.y;
    int h = blockIdx.x * 128 + threadIdx.x;
    const float* C = c_out + (size_t)b * LC * H2;
    const float* w = batt + (size_t)b * LC;
    float acc = 0.f;
    for (int cc = 0; cc < LC; ++cc) acc += w[cc] * C[(size_t)cc * H2 + h];
    q2c[(size_t)b * H2 + h] = acc;
}

__global__ void build_G(const float* __restrict__ c_out, const float* __restrict__ c2q,
                        const float* __restrict__ q2c, float* __restrict__ G)
{
    size_t i = (size_t)blockIdx.x * blockDim.x + threadIdx.x;
    const size_t total = (size_t)BB * LC * (H2 / 4);
    if (i >= total) return;
    int h4 = (int)(i % (H2 / 4));
    size_t r = i / (H2 / 4);
    int b = (int)(r / LC);
    float4 co = ((const float4*)c_out)[r * (H2 / 4) + h4];
    float4 cq = ((const float4*)c2q)[r * (H2 / 4) + h4];
    float4 q2 = ((const float4*)q2c)[(size_t)b * (H2 / 4) + h4];
    float4* Gr = (float4*)(G + r * H8);
    Gr[h4] = make_float4(rtf(co.x), rtf(co.y), rtf(co.z), rtf(co.w));
    Gr[(H2 / 4) + h4] = make_float4(rtf(cq.x), rtf(cq.y), rtf(cq.z), rtf(cq.w));
    Gr[2 * (H2 / 4) + h4] = make_float4(rtf(co.x * cq.x), rtf(co.y * cq.y),
                                        rtf(co.z * cq.z), rtf(co.w * cq.w));
    Gr[3 * (H2 / 4) + h4] = make_float4(rtf(co.x * q2.x), rtf(co.y * q2.y),
                                        rtf(co.z * q2.z), rtf(co.w * q2.w));
}

// ---------------------------------------------------------------------------
extern "C" void kernel_launch(void* const* d_in, const int* in_sizes, int n_in,
                              void* d_out, int out_size)
{
    const int*   q       = (const int*)  d_in[0];
    const int*   c       = (const int*)  d_in[1];
    const float* emb     = (const float*)d_in[2];
    const float* Wih_q   = (const float*)d_in[3];
    const float* Whh_q   = (const float*)d_in[4];
    const float* b_q     = (const float*)d_in[5];
    const float* Wih_c   = (const float*)d_in[6];
    const float* Whh_c   = (const float*)d_in[7];
    const float* b_c     = (const float*)d_in[8];
    const float* Wih_m   = (const float*)d_in[9];
    const float* Whh_m   = (const float*)d_in[10];
    const float* b_m     = (const float*)d_in[11];
    const float* sim_w   = (const float*)d_in[12];
    const float* sim_b   = (const float*)d_in[13];
    const float* start_w = (const float*)d_in[14];
    const float* start_b = (const float*)d_in[15];
    const float* end_w   = (const float*)d_in[16];
    const float* end_b   = (const float*)d_in[17];
    float* out = (float*)d_out;

    float *qemb, *cemb, *xw, *xwq, *qout, *cout, *S, *smax, *batt, *cw, *qw, *c2q, *q2c, *G, *M, *wcvt, *whh;
    cudaGetSymbolAddress((void**)&qemb, g_qemb);
    cudaGetSymbolAddress((void**)&cemb, g_cemb);
    cudaGetSymbolAddress((void**)&xw,   g_xw);
    cudaGetSymbolAddress((void**)&xwq,  g_xwq);
    cudaGetSymbolAddress((void**)&qout, g_qout);
    cudaGetSymbolAddress((void**)&cout, g_cout);
    cudaGetSymbolAddress((void**)&S,    g_S);
    cudaGetSymbolAddress((void**)&smax, g_smax);
    cudaGetSymbolAddress((void**)&batt, g_batt);
    cudaGetSymbolAddress((void**)&cw,   g_cw);
    cudaGetSymbolAddress((void**)&qw,   g_qw);
    cudaGetSymbolAddress((void**)&c2q,  g_c2q);
    cudaGetSymbolAddress((void**)&q2c,  g_q2c);
    cudaGetSymbolAddress((void**)&G,    g_G);
    cudaGetSymbolAddress((void**)&M,    g_M);
    cudaGetSymbolAddress((void**)&wcvt, g_wcvt);
    cudaGetSymbolAddress((void**)&whh,  g_whh);

    cudaFuncSetAttribute(lstm_scan2, cudaFuncAttributeMaxDynamicSharedMemorySize, SCAN_SMEM);
    cudaFuncSetAttribute(gemm_tf32, cudaFuncAttributeMaxDynamicSharedMemorySize, GEMM_SMEM);

    gather_emb<<<(BB * LQ * EE + 255) / 256, 256>>>(q, emb, qemb, BB * LQ * EE);
    gather_emb<<<(BB * LC * EE + 255) / 256, 256>>>(c, emb, cemb, BB * LC * EE);

    // q projection -> xwq ; c projection -> xw ; then one merged scan
    cvt_tf32<<<(2 * G4 * EE + 255) / 256, 256>>>(Wih_q, wcvt, 2 * G4 * EE);
    cvt_tf32<<<(2 * G4 * HH + 255) / 256, 256>>>(Whh_q, whh + (size_t)2 * G4 * HH, 2 * G4 * HH);
    for (int d = 0; d < 2; ++d)
        gemm_tf32<<<dim3(G4 / 128, (BB * LQ) / 128), 128, GEMM_SMEM>>>(
            qemb, wcvt + (size_t)d * G4 * EE, b_q + (size_t)d * G4,
            xwq + (size_t)d * BB * LQ * G4, BB * LQ, G4, EE);
    cvt_tf32<<<(2 * G4 * EE + 255) / 256, 256>>>(Wih_c, wcvt, 2 * G4 * EE);
    cvt_tf32<<<(2 * G4 * HH + 255) / 256, 256>>>(Whh_c, whh, 2 * G4 * HH);
    for (int d = 0; d < 2; ++d)
        gemm_tf32<<<dim3(G4 / 128, (BB * LC) / 128), 128, GEMM_SMEM>>>(
            cemb, wcvt + (size_t)d * G4 * EE, b_c + (size_t)d * G4,
            xw + (size_t)d * BB * LC * G4, BB * LC, G4, EE);
    lstm_scan2<<<128, 256, SCAN_SMEM>>>(xw, whh, cout, LC,
                                        xwq, whh + (size_t)2 * G4 * HH, qout, LQ);

    // attention
    rowdot<<<(BB * LC) / 8, 256>>>(cout, sim_w, nullptr, cw, BB * LC);
    rowdot<<<(BB * LQ) / 8, 256>>>(qout, sim_w + H2, nullptr, qw, BB * LQ);
    attn_S<<<dim3(LC / 64, BB), 256>>>(cout, qout, sim_w, sim_b, cw, qw, S);
    softmax64<<<(BB * LC) / 8, 256>>>(S, smax, BB * LC);
    softmax512<<<BB, 512>>>(smax, batt);
    attn_c2q<<<dim3(H2 / 64, LC / 64, BB), 256>>>(S, qout, c2q);
    attn_q2c<<<dim3(H2 / 128, BB), 128>>>(batt, cout, q2c);
    build_G<<<(int)(((size_t)BB * LC * (H2 / 4) + 255) / 256), 256>>>(cout, c2q, q2c, G);

    // modeling BiLSTM (single group)
    cvt_tf32<<<(2 * G4 * H8 + 255) / 256, 256>>>(Wih_m, wcvt, 2 * G4 * H8);
    cvt_tf32<<<(2 * G4 * HH + 255) / 256, 256>>>(Whh_m, whh, 2 * G4 * HH);
    for (int d = 0; d < 2; ++d)
        gemm_tf32<<<dim3(G4 / 128, (BB * LC) / 128), 128, GEMM_SMEM>>>(
            G, wcvt + (size_t)d * G4 * H8, b_m + (size_t)d * G4,
            xw + (size_t)d * BB * LC * G4, BB * LC, G4, H8);
    lstm_scan2<<<64, 256, SCAN_SMEM>>>(xw, whh, M, LC, xw, whh, M, LC);

    rowdot<<<(BB * LC) / 8, 256>>>(M, start_w, start_b, out, BB * LC);
    rowdot<<<(BB * LC) / 8, 256>>>(M, end_w, end_b, out + (size_t)BB * LC, BB * LC);
}

// round 14
// speedup vs baseline: 1.3151x; 1.0063x over previous
#include <cuda_runtime.h>
#include <cuda_bf16.h>
#include <math.h>
#include <stdint.h>

#define EE   300
#define HH   256
#define G4   1024
#define H2   512
#define H8   2048
#define BB   64
#define LQ   64
#define LC   512

__device__ float g_qemb[(size_t)BB * LQ * EE];
__device__ float g_cemb[(size_t)BB * LC * EE];
__device__ float g_xw  [(size_t)2 * BB * LC * G4];
__device__ float g_xwq [(size_t)2 * BB * LQ * G4];
__device__ float g_qout[(size_t)BB * LQ * H2];
__device__ float g_cout[(size_t)BB * LC * H2];
__device__ float g_S   [(size_t)BB * LC * LQ];
__device__ float g_smax[(size_t)BB * LC];
__device__ float g_batt[(size_t)BB * LC];
__device__ float g_cw  [(size_t)BB * LC];
__device__ float g_qw  [(size_t)BB * LQ];
__device__ float g_c2q [(size_t)BB * LC * H2];
__device__ float g_q2c [(size_t)BB * H2];
__device__ float g_G   [(size_t)BB * LC * H8];
__device__ float g_M   [(size_t)BB * LC * H2];
__device__ float g_h   [(size_t)4 * HH * BB];
__device__ float g_wcvt[(size_t)2 * G4 * H8];
__device__ float g_whh [(size_t)4 * G4 * HH];
__device__ unsigned g_bar_cnt2[2] = {0, 0};
__device__ unsigned g_bar_gen2[2] = {0, 0};

__device__ __forceinline__ float sigmoidf_(float x) { return 1.f / (1.f + expf(-x)); }

__device__ __forceinline__ uint32_t f2tf32(float x)
{
    uint32_t r;
    asm("cvt.rna.tf32.f32 %0, %1;" : "=r"(r) : "f"(x));
    return r;
}
__device__ __forceinline__ float rtf(float x) { return __uint_as_float(f2tf32(x)); }

__device__ __forceinline__ void grid_barrier_g(int grp, unsigned nb)
{
    __syncthreads();
    if (threadIdx.x == 0) {
        asm volatile("fence.acq_rel.gpu;" ::: "memory");
        unsigned g = *(volatile unsigned*)&g_bar_gen2[grp];
        if (atomicAdd(&g_bar_cnt2[grp], 1u) == nb - 1u) {
            g_bar_cnt2[grp] = 0;
            __threadfence();
            atomicAdd(&g_bar_gen2[grp], 1u);
        } else {
            while (*(volatile unsigned*)&g_bar_gen2[grp] == g) { }
        }
        asm volatile("fence.acq_rel.gpu;" ::: "memory");
    }
    __syncthreads();
}

__device__ __forceinline__ void cp16(uint32_t dst, const void* src)
{
    asm volatile("cp.async.cg.shared.global [%0], [%1], 16;" :: "r"(dst), "l"(src));
}
__device__ __forceinline__ uint32_t smem_u32(const void* p)
{
    uint32_t a;
    asm("{ .reg .u64 t; cvta.to.shared.u64 t, %1; cvt.u32.u64 %0, t; }" : "=r"(a) : "l"(p));
    return a;
}

// ---------------------------------------------------------------------------
__global__ void gather_emb(const int* __restrict__ tok, const float* __restrict__ emb,
                           float* __restrict__ out, int total)
{
    int i = blockIdx.x * blockDim.x + threadIdx.x;
    if (i >= total) return;
    int row = i / EE;
    int e   = i - row * EE;
    out[i] = rtf(emb[(size_t)tok[row] * EE + e]);
}

__global__ void cvt_tf32(const float* __restrict__ in, float* __restrict__ out, int n)
{
    int i = blockIdx.x * blockDim.x + threadIdx.x;
    if (i < n) out[i] = rtf(in[i]);
}

// ---------------------------------------------------------------------------
// tf32 mma.sync GEMM v4: C=A[M,K]*B[N,K]^T + bias.
// CTA 128x128, 4 warps, warp tile 64x64, BK=32.
// 3-stage cp.async ring, ONE __syncthreads per k-tile (fills issued after
// sync, before compute; stage kt+2 == stage kt-1 already consumed).
// ---------------------------------------------------------------------------
#define SROW 36
#define STILE (128 * SROW)
#define GSTAGE (2 * STILE)                       // floats per stage (A+B)
#define GEMM_SMEM (3 * GSTAGE * (int)sizeof(float))   // 110592 B

__device__ __forceinline__ void fill_tile(uint32_t sA, uint32_t sB,
                                          const float* __restrict__ A,
                                          const float* __restrict__ B,
                                          int bm, int bn, int K, int k0, int tid)
{
#pragma unroll
    for (int i = 0; i < 8; ++i) {
        int idx = tid + i * 128;
        int row = idx >> 3, c4 = idx & 7;
        int k = k0 + c4 * 4;
        uint32_t da = sA + (row * SROW + c4 * 4) * 4;
        uint32_t db = sB + (row * SROW + c4 * 4) * 4;
        if (k + 4 <= K) {
            cp16(da, &A[(size_t)(bm + row) * K + k]);
            cp16(db, &B[(size_t)(bn + row) * K + k]);
        } else {
            asm volatile("st.shared.v4.b32 [%0], {%1,%1,%1,%1};" :: "r"(da), "r"(0) : "memory");
            asm volatile("st.shared.v4.b32 [%0], {%1,%1,%1,%1};" :: "r"(db), "r"(0) : "memory");
        }
    }
}

__global__ void __launch_bounds__(128)
gemm_tf32(const float* __restrict__ A, const float* __restrict__ B,
          const float* __restrict__ bias, float* __restrict__ C,
          int M, int N, int K)
{
    extern __shared__ float sh[];
    const int tid  = threadIdx.x;
    const int lane = tid & 31;
    const int warp = tid >> 5;
    const int g = lane >> 2, t = lane & 3;
    const int m0 = (warp & 1) * 64;
    const int n0 = (warp >> 1) * 64;
    const int bm = blockIdx.y * 128;
    const int bn = blockIdx.x * 128;
    const uint32_t sb = smem_u32(sh);

    float acc[4][8][4];
#pragma unroll
    for (int mi = 0; mi < 4; ++mi)
#pragma unroll
        for (int ni = 0; ni < 8; ++ni)
#pragma unroll
            for (int k = 0; k < 4; ++k) acc[mi][ni][k] = 0.f;

    const int nk = (K + 31) >> 5;
    const uint32_t stage_b = GSTAGE * 4;

    // prologue: stages 0 and 1
    fill_tile(sb, sb + STILE * 4, A, B, bm, bn, K, 0, tid);
    asm volatile("cp.async.commit_group;" ::: "memory");
    if (nk > 1)
        fill_tile(sb + stage_b, sb + stage_b + STILE * 4, A, B, bm, bn, K, 32, tid);
    asm volatile("cp.async.commit_group;" ::: "memory");

    for (int kt = 0; kt < nk; ++kt) {
        const int s = kt % 3;
        asm volatile("cp.async.wait_group 1;" ::: "memory");
        __syncthreads();
        if (kt + 2 < nk) {
            const int s2 = (kt + 2) % 3;
            fill_tile(sb + s2 * stage_b, sb + s2 * stage_b + STILE * 4,
                      A, B, bm, bn, K, (kt + 2) * 32, tid);
        }
        asm volatile("cp.async.commit_group;" ::: "memory");

        const float* Ab = sh + s * GSTAGE;
        const float* Bb = Ab + STILE;
#pragma unroll
        for (int kk = 0; kk < 32; kk += 8) {
            uint32_t af[4][4];
#pragma unroll
            for (int mi = 0; mi < 4; ++mi) {
                const float* ap = Ab + (m0 + mi * 16) * SROW + kk;
                af[mi][0] = __float_as_uint(ap[g * SROW + t]);
                af[mi][1] = __float_as_uint(ap[(g + 8) * SROW + t]);
                af[mi][2] = __float_as_uint(ap[g * SROW + t + 4]);
                af[mi][3] = __float_as_uint(ap[(g + 8) * SROW + t + 4]);
            }
            uint32_t bf[8][2];
#pragma unroll
            for (int ni = 0; ni < 8; ++ni) {
                const float* bp = Bb + (n0 + ni * 8) * SROW + kk;
                bf[ni][0] = __float_as_uint(bp[g * SROW + t]);
                bf[ni][1] = __float_as_uint(bp[g * SROW + t + 4]);
            }
#pragma unroll
            for (int mi = 0; mi < 4; ++mi)
#pragma unroll
                for (int ni = 0; ni < 8; ++ni)
                    asm volatile(
                        "mma.sync.aligned.m16n8k8.row.col.f32.tf32.tf32.f32 "
                        "{%0,%1,%2,%3}, {%4,%5,%6,%7}, {%8,%9}, {%0,%1,%2,%3};\n"
                        : "+f"(acc[mi][ni][0]), "+f"(acc[mi][ni][1]),
                          "+f"(acc[mi][ni][2]), "+f"(acc[mi][ni][3])
                        : "r"(af[mi][0]), "r"(af[mi][1]), "r"(af[mi][2]), "r"(af[mi][3]),
                          "r"(bf[ni][0]), "r"(bf[ni][1]));
        }
    }

#pragma unroll
    for (int mi = 0; mi < 4; ++mi) {
#pragma unroll
        for (int ni = 0; ni < 8; ++ni) {
            int row0 = bm + m0 + mi * 16 + g;
            int col  = bn + n0 + ni * 8 + t * 2;
            float2 bv = make_float2(0.f, 0.f);
            if (bias) bv = *(const float2*)&bias[col];
            *(float2*)&C[(size_t)row0 * N + col] =
                make_float2(acc[mi][ni][0] + bv.x, acc[mi][ni][1] + bv.y);
            *(float2*)&C[(size_t)(row0 + 8) * N + col] =
                make_float2(acc[mi][ni][2] + bv.x, acc[mi][ni][3] + bv.y);
        }
    }
}

// ---------------------------------------------------------------------------
// BiLSTM scan, tensor-core recurrence, two independent barrier groups.
// ---------------------------------------------------------------------------
#define LPAD 72
#define SC_H   (HH * LPAD)
#define SC_XW  (SC_H + BB * 33)
#define SC_TOT (SC_XW + BB * 33)
#define SCAN_SMEM (SC_TOT * (int)sizeof(float))   // 90624 B

__global__ void __launch_bounds__(256)
lstm_scan2(const float* __restrict__ xW0, const float* __restrict__ Whh0,
           float* __restrict__ out0, int T0,
           const float* __restrict__ xW1, const float* __restrict__ Whh1,
           float* __restrict__ out1, int T1)
{
    extern __shared__ float sh[];
    float* h_sh  = sh;
    float* xw_sh = sh + SC_H;
    float* P_sh  = sh + SC_XW;

    const int tid  = threadIdx.x;
    const int lane = tid & 31;
    const int warp = tid >> 5;
    const int g = lane >> 2, t = lane & 3;
    const int nt  = warp >> 1;
    const int mtp = warp & 1;
    const int grp = blockIdx.x >> 6;
    const int bid = blockIdx.x & 63;
    const int dir = bid >> 5;
    const int j0  = (bid & 31) * 8;

    const float* xWall = grp ? xW1 : xW0;
    const float* Whh   = grp ? Whh1 : Whh0;
    float*       outp  = grp ? out1 : out0;
    const int    T     = grp ? T1 : T0;

    float wreg[64];
    {
        const float* Wd = Whh + (size_t)dir * G4 * HH + (size_t)(nt * HH + j0 + g) * HH;
#pragma unroll
        for (int kt = 0; kt < 32; ++kt) {
            wreg[2 * kt]     = Wd[kt * 8 + t];
            wreg[2 * kt + 1] = Wd[kt * 8 + t + 4];
        }
    }

    const float* xWD = xWall + (size_t)dir * BB * T * G4;
    float*       hD  = g_h + (size_t)(grp * 2 + dir) * HH * BB;
    const int eb = tid & 63, eu = tid >> 6;
    float cst[2] = {0.f, 0.f};

    for (int s = 0; s < T; ++s) {
        const int tt = dir ? (T - 1 - s) : s;
        {
            const float* src = &xWD[((size_t)eb * T + tt) * G4 + eu * HH + j0];
            float4 v0 = *(const float4*)src;
            float4 v1 = *(const float4*)(src + 4);
            float* d = &xw_sh[eb * 33 + eu * 8];
            d[0] = v0.x; d[1] = v0.y; d[2] = v0.z; d[3] = v0.w;
            d[4] = v1.x; d[5] = v1.y; d[6] = v1.z; d[7] = v1.w;
        }
        if (s > 0) {
            const float4* h4 = (const float4*)hD;
#pragma unroll
            for (int i = 0; i < 16; ++i) {
                int idx4 = tid + i * 256;
                int j = idx4 >> 4, b4 = (idx4 & 15) << 2;
                float4 v = __ldcg(h4 + idx4);
                *(float4*)&h_sh[j * LPAD + b4] = v;
            }
        }
        __syncthreads();

        float cf[2][4] = {{0.f, 0.f, 0.f, 0.f}, {0.f, 0.f, 0.f, 0.f}};
        if (s > 0) {
#pragma unroll
            for (int kt = 0; kt < 32; ++kt) {
                const float* hr0 = &h_sh[(kt * 8 + t) * LPAD];
                const float* hr1 = &h_sh[(kt * 8 + t + 4) * LPAD];
                uint32_t b0 = __float_as_uint(wreg[2 * kt]);
                uint32_t b1 = __float_as_uint(wreg[2 * kt + 1]);
#pragma unroll
                for (int p = 0; p < 2; ++p) {
                    int mb = mtp * 16 + p * 32;
                    uint32_t a0 = __float_as_uint(hr0[mb + g]);
                    uint32_t a1 = __float_as_uint(hr0[mb + g + 8]);
                    uint32_t a2 = __float_as_uint(hr1[mb + g]);
                    uint32_t a3 = __float_as_uint(hr1[mb + g + 8]);
                    asm volatile(
                        "mma.sync.aligned.m16n8k8.row.col.f32.tf32.tf32.f32 "
                        "{%0,%1,%2,%3}, {%4,%5,%6,%7}, {%8,%9}, {%0,%1,%2,%3};\n"
                        : "+f"(cf[p][0]), "+f"(cf[p][1]), "+f"(cf[p][2]), "+f"(cf[p][3])
                        : "r"(a0), "r"(a1), "r"(a2), "r"(a3), "r"(b0), "r"(b1));
                }
            }
        }
#pragma unroll
        for (int p = 0; p < 2; ++p) {
            int mb = mtp * 16 + p * 32;
            int cc = nt * 8 + 2 * t;
            P_sh[(mb + g) * 33 + cc]     = cf[p][0];
            P_sh[(mb + g) * 33 + cc + 1] = cf[p][1];
            P_sh[(mb + g + 8) * 33 + cc]     = cf[p][2];
            P_sh[(mb + g + 8) * 33 + cc + 1] = cf[p][3];
        }
        __syncthreads();

#pragma unroll
        for (int u = 0; u < 2; ++u) {
            int ju = eu + u * 4;
            const float* Pr = &P_sh[eb * 33];
            const float* Xr = &xw_sh[eb * 33];
            float pi = Pr[ju]      + Xr[ju];
            float pf = Pr[8 + ju]  + Xr[8 + ju];
            float pg = Pr[16 + ju] + Xr[16 + ju];
            float po = Pr[24 + ju] + Xr[24 + ju];
            float ig = sigmoidf_(pi);
            float fg = sigmoidf_(pf);
            float gg = tanhf(pg);
            float og = sigmoidf_(po);
            cst[u] = fg * cst[u] + ig * gg;
            float hh = og * tanhf(cst[u]);
            __stcg(&hD[(j0 + ju) * BB + eb], rtf(hh));
            outp[((size_t)eb * T + tt) * H2 + dir * HH + j0 + ju] = hh;
        }
        if (s + 1 < T) grid_barrier_g(grp, 64);
    }
}

// ---------------------------------------------------------------------------
__global__ void rowdot(const float* __restrict__ A, const float* __restrict__ w,
                       const float* __restrict__ bias, float* __restrict__ out, int rows)
{
    int gw = (blockIdx.x * blockDim.x + threadIdx.x) >> 5;
    int lane = threadIdx.x & 31;
    if (gw >= rows) return;
    const float* row = A + (size_t)gw * H2;
    float s = 0.f;
#pragma unroll
    for (int i = 0; i < 16; ++i) s += row[lane + i * 32] * w[lane + i * 32];
#pragma unroll
    for (int off = 16; off; off >>= 1) s += __shfl_xor_sync(0xffffffffu, s, off);
    if (lane == 0) out[gw] = s + (bias ? bias[0] : 0.f);
}

// both heads in one pass over M
__global__ void rowdot2(const float* __restrict__ A,
                        const float* __restrict__ w0, const float* __restrict__ b0,
                        const float* __restrict__ w1, const float* __restrict__ b1,
                        float* __restrict__ o0, float* __restrict__ o1, int rows)
{
    int gw = (blockIdx.x * blockDim.x + threadIdx.x) >> 5;
    int lane = threadIdx.x & 31;
    if (gw >= rows) return;
    const float* row = A + (size_t)gw * H2;
    float s0 = 0.f, s1 = 0.f;
#pragma unroll
    for (int i = 0; i < 16; ++i) {
        float v = row[lane + i * 32];
        s0 += v * w0[lane + i * 32];
        s1 += v * w1[lane + i * 32];
    }
#pragma unroll
    for (int off = 16; off; off >>= 1) {
        s0 += __shfl_xor_sync(0xffffffffu, s0, off);
        s1 += __shfl_xor_sync(0xffffffffu, s1, off);
    }
    if (lane == 0) {
        o0[gw] = s0 + b0[0];
        o1[gw] = s1 + b1[0];
    }
}

__global__ void __launch_bounds__(256)
attn_S(const float* __restrict__ c_out, const float* __restrict__ q_out,
       const float* __restrict__ sim_w, const float* __restrict__ sim_b,
       const float* __restrict__ cw, const float* __restrict__ qw,
       float* __restrict__ S)
{
    __shared__ float As[16][68];
    __shared__ float Bs[16][68];
    const int b = blockIdx.y, cc0 = blockIdx.x * 64;
    const float* A  = c_out + ((size_t)b * LC + cc0) * H2;
    const float* Bq = q_out + (size_t)b * LQ * H2;
    const float* wcq = sim_w + 2 * H2;
    const int tid = threadIdx.x;
    const int lr = tid >> 2, lk4 = (tid & 3) * 4;
    const int tx = tid & 15, ty = tid >> 4;
    float acc[4][4];
#pragma unroll
    for (int i = 0; i < 4; ++i)
#pragma unroll
        for (int j = 0; j < 4; ++j) acc[i][j] = 0.f;

    for (int k0 = 0; k0 < H2; k0 += 16) {
        float4 va = *(const float4*)&A[(size_t)lr * H2 + k0 + lk4];
        float4 wv = *(const float4*)&wcq[k0 + lk4];
        As[lk4 + 0][lr] = va.x * wv.x;
        As[lk4 + 1][lr] = va.y * wv.y;
        As[lk4 + 2][lr] = va.z * wv.z;
        As[lk4 + 3][lr] = va.w * wv.w;
        float4 vb = *(const float4*)&Bq[(size_t)lr * H2 + k0 + lk4];
        Bs[lk4 + 0][lr] = vb.x;
        Bs[lk4 + 1][lr] = vb.y;
        Bs[lk4 + 2][lr] = vb.z;
        Bs[lk4 + 3][lr] = vb.w;
        __syncthreads();
#pragma unroll
        for (int k = 0; k < 16; ++k) {
            float4 av = *(const float4*)&As[k][ty * 4];
            float4 bv = *(const float4*)&Bs[k][tx * 4];
            float am[4] = {av.x, av.y, av.z, av.w};
            float bn[4] = {bv.x, bv.y, bv.z, bv.w};
#pragma unroll
            for (int i = 0; i < 4; ++i)
#pragma unroll
                for (int j = 0; j < 4; ++j) acc[i][j] += am[i] * bn[j];
        }
        __syncthreads();
    }
    float sb = sim_b[0];
#pragma unroll
    for (int i = 0; i < 4; ++i) {
        int cc = cc0 + ty * 4 + i;
        float cwv = cw[b * LC + cc];
#pragma unroll
        for (int j = 0; j < 4; ++j) {
            int qq = tx * 4 + j;
            S[((size_t)b * LC + cc) * LQ + qq] = acc[i][j] + cwv + qw[b * LQ + qq] + sb;
        }
    }
}

__global__ void softmax64(float* __restrict__ S, float* __restrict__ smax, int rows)
{
    int gw = (blockIdx.x * blockDim.x + threadIdx.x) >> 5;
    int lane = threadIdx.x & 31;
    if (gw >= rows) return;
    float* row = S + (size_t)gw * LQ;
    float v0 = row[lane], v1 = row[lane + 32];
    float m = fmaxf(v0, v1);
#pragma unroll
    for (int off = 16; off; off >>= 1) m = fmaxf(m, __shfl_xor_sync(0xffffffffu, m, off));
    float e0 = expf(v0 - m), e1 = expf(v1 - m);
    float s = e0 + e1;
#pragma unroll
    for (int off = 16; off; off >>= 1) s += __shfl_xor_sync(0xffffffffu, s, off);
    float inv = 1.f / s;
    row[lane] = e0 * inv;
    row[lane + 32] = e1 * inv;
    if (lane == 0) smax[gw] = m;
}

__global__ void softmax512(const float* __restrict__ in, float* __restrict__ outv)
{
    __shared__ float red[16];
    int b = blockIdx.x, tid = threadIdx.x;
    float v = in[(size_t)b * LC + tid];
    float m = v;
#pragma unroll
    for (int off = 16; off; off >>= 1) m = fmaxf(m, __shfl_xor_sync(0xffffffffu, m, off));
    if ((tid & 31) == 0) red[tid >> 5] = m;
    __syncthreads();
    if (tid == 0) {
        float x = red[0];
        for (int i = 1; i < 16; ++i) x = fmaxf(x, red[i]);
        red[0] = x;
    }
    __syncthreads();
    m = red[0];
    __syncthreads();
    float e = expf(v - m);
    float s = e;
#pragma unroll
    for (int off = 16; off; off >>= 1) s += __shfl_xor_sync(0xffffffffu, s, off);
    if ((tid & 31) == 0) red[tid >> 5] = s;
    __syncthreads();
    if (tid == 0) {
        float x = 0.f;
        for (int i = 0; i < 16; ++i) x += red[i];
        red[0] = x;
    }
    __syncthreads();
    outv[(size_t)b * LC + tid] = e / red[0];
}

__global__ void __launch_bounds__(256)
attn_c2q(const float* __restrict__ a, const float* __restrict__ q_out,
         float* __restrict__ c2q)
{
    __shared__ float As[16][68];
    __shared__ float Bs[16][68];
    const int b = blockIdx.z, cc0 = blockIdx.y * 64, h0 = blockIdx.x * 64;
    const float* A = a + ((size_t)b * LC + cc0) * LQ;
    const float* B = q_out + (size_t)b * LQ * H2;
    const int tid = threadIdx.x;
    const int lr = tid >> 2, lk4 = (tid & 3) * 4;
    const int bk = tid >> 4, bn4 = (tid & 15) * 4;
    const int tx = tid & 15, ty = tid >> 4;
    float acc[4][4];
#pragma unroll
    for (int i = 0; i < 4; ++i)
#pragma unroll
        for (int j = 0; j < 4; ++j) acc[i][j] = 0.f;

    for (int k0 = 0; k0 < LQ; k0 += 16) {
        float4 va = *(const float4*)&A[(size_t)lr * LQ + k0 + lk4];
        As[lk4 + 0][lr] = va.x;
        As[lk4 + 1][lr] = va.y;
        As[lk4 + 2][lr] = va.z;
        As[lk4 + 3][lr] = va.w;
        float4 vb = *(const float4*)&B[(size_t)(k0 + bk) * H2 + h0 + bn4];
        *(float4*)&Bs[bk][bn4] = vb;
        __syncthreads();
#pragma unroll
        for (int k = 0; k < 16; ++k) {
            float4 av = *(const float4*)&As[k][ty * 4];
            float4 bv = *(const float4*)&Bs[k][tx * 4];
            float am[4] = {av.x, av.y, av.z, av.w};
            float bn[4] = {bv.x, bv.y, bv.z, bv.w};
#pragma unroll
            for (int i = 0; i < 4; ++i)
#pragma unroll
                for (int j = 0; j < 4; ++j) acc[i][j] += am[i] * bn[j];
        }
        __syncthreads();
    }
#pragma unroll
    for (int i = 0; i < 4; ++i)
#pragma unroll
        for (int j = 0; j < 4; ++j)
            c2q[((size_t)b * LC + cc0 + ty * 4 + i) * H2 + h0 + tx * 4 + j] = acc[i][j];
}

__global__ void attn_q2c(const float* __restrict__ batt, const float* __restrict__ c_out,
                         float* __restrict__ q2c)
{
    int b = blockIdx.y;
    int h = blockIdx.x * 128 + threadIdx.x;
    const float* C = c_out + (size_t)b * LC * H2;
    const float* w = batt + (size_t)b * LC;
    float acc = 0.f;
    for (int cc = 0; cc < LC; ++cc) acc += w[cc] * C[(size_t)cc * H2 + h];
    q2c[(size_t)b * H2 + h] = acc;
}

__global__ void build_G(const float* __restrict__ c_out, const float* __restrict__ c2q,
                        const float* __restrict__ q2c, float* __restrict__ G)
{
    size_t i = (size_t)blockIdx.x * blockDim.x + threadIdx.x;
    const size_t total = (size_t)BB * LC * (H2 / 4);
    if (i >= total) return;
    int h4 = (int)(i % (H2 / 4));
    size_t r = i / (H2 / 4);
    int b = (int)(r / LC);
    float4 co = ((const float4*)c_out)[r * (H2 / 4) + h4];
    float4 cq = ((const float4*)c2q)[r * (H2 / 4) + h4];
    float4 q2 = ((const float4*)q2c)[(size_t)b * (H2 / 4) + h4];
    float4* Gr = (float4*)(G + r * H8);
    Gr[h4] = make_float4(rtf(co.x), rtf(co.y), rtf(co.z), rtf(co.w));
    Gr[(H2 / 4) + h4] = make_float4(rtf(cq.x), rtf(cq.y), rtf(cq.z), rtf(cq.w));
    Gr[2 * (H2 / 4) + h4] = make_float4(rtf(co.x * cq.x), rtf(co.y * cq.y),
                                        rtf(co.z * cq.z), rtf(co.w * cq.w));
    Gr[3 * (H2 / 4) + h4] = make_float4(rtf(co.x * q2.x), rtf(co.y * q2.y),
                                        rtf(co.z * q2.z), rtf(co.w * q2.w));
}

// ---------------------------------------------------------------------------
extern "C" void kernel_launch(void* const* d_in, const int* in_sizes, int n_in,
                              void* d_out, int out_size)
{
    const int*   q       = (const int*)  d_in[0];
    const int*   c       = (const int*)  d_in[1];
    const float* emb     = (const float*)d_in[2];
    const float* Wih_q   = (const float*)d_in[3];
    const float* Whh_q   = (const float*)d_in[4];
    const float* b_q     = (const float*)d_in[5];
    const float* Wih_c   = (const float*)d_in[6];
    const float* Whh_c   = (const float*)d_in[7];
    const float* b_c     = (const float*)d_in[8];
    const float* Wih_m   = (const float*)d_in[9];
    const float* Whh_m   = (const float*)d_in[10];
    const float* b_m     = (const float*)d_in[11];
    const float* sim_w   = (const float*)d_in[12];
    const float* sim_b   = (const float*)d_in[13];
    const float* start_w = (const float*)d_in[14];
    const float* start_b = (const float*)d_in[15];
    const float* end_w   = (const float*)d_in[16];
    const float* end_b   = (const float*)d_in[17];
    float* out = (float*)d_out;

    float *qemb, *cemb, *xw, *xwq, *qout, *cout, *S, *smax, *batt, *cw, *qw, *c2q, *q2c, *G, *M, *wcvt, *whh;
    cudaGetSymbolAddress((void**)&qemb, g_qemb);
    cudaGetSymbolAddress((void**)&cemb, g_cemb);
    cudaGetSymbolAddress((void**)&xw,   g_xw);
    cudaGetSymbolAddress((void**)&xwq,  g_xwq);
    cudaGetSymbolAddress((void**)&qout, g_qout);
    cudaGetSymbolAddress((void**)&cout, g_cout);
    cudaGetSymbolAddress((void**)&S,    g_S);
    cudaGetSymbolAddress((void**)&smax, g_smax);
    cudaGetSymbolAddress((void**)&batt, g_batt);
    cudaGetSymbolAddress((void**)&cw,   g_cw);
    cudaGetSymbolAddress((void**)&qw,   g_qw);
    cudaGetSymbolAddress((void**)&c2q,  g_c2q);
    cudaGetSymbolAddress((void**)&q2c,  g_q2c);
    cudaGetSymbolAddress((void**)&G,    g_G);
    cudaGetSymbolAddress((void**)&M,    g_M);
    cudaGetSymbolAddress((void**)&wcvt, g_wcvt);
    cudaGetSymbolAddress((void**)&whh,  g_whh);

    cudaFuncSetAttribute(lstm_scan2, cudaFuncAttributeMaxDynamicSharedMemorySize, SCAN_SMEM);
    cudaFuncSetAttribute(gemm_tf32, cudaFuncAttributeMaxDynamicSharedMemorySize, GEMM_SMEM);

    gather_emb<<<(BB * LQ * EE + 255) / 256, 256>>>(q, emb, qemb, BB * LQ * EE);
    gather_emb<<<(BB * LC * EE + 255) / 256, 256>>>(c, emb, cemb, BB * LC * EE);

    // q projection -> xwq ; c projection -> xw ; merged scan
    cvt_tf32<<<(2 * G4 * EE + 255) / 256, 256>>>(Wih_q, wcvt, 2 * G4 * EE);
    cvt_tf32<<<(2 * G4 * HH + 255) / 256, 256>>>(Whh_q, whh + (size_t)2 * G4 * HH, 2 * G4 * HH);
    for (int d = 0; d < 2; ++d)
        gemm_tf32<<<dim3(G4 / 128, (BB * LQ) / 128), 128, GEMM_SMEM>>>(
            qemb, wcvt + (size_t)d * G4 * EE, b_q + (size_t)d * G4,
            xwq + (size_t)d * BB * LQ * G4, BB * LQ, G4, EE);
    cvt_tf32<<<(2 * G4 * EE + 255) / 256, 256>>>(Wih_c, wcvt, 2 * G4 * EE);
    cvt_tf32<<<(2 * G4 * HH + 255) / 256, 256>>>(Whh_c, whh, 2 * G4 * HH);
    for (int d = 0; d < 2; ++d)
        gemm_tf32<<<dim3(G4 / 128, (BB * LC) / 128), 128, GEMM_SMEM>>>(
            cemb, wcvt + (size_t)d * G4 * EE, b_c + (size_t)d * G4,
            xw + (size_t)d * BB * LC * G4, BB * LC, G4, EE);
    lstm_scan2<<<128, 256, SCAN_SMEM>>>(xw, whh, cout, LC,
                                        xwq, whh + (size_t)2 * G4 * HH, qout, LQ);

    // attention
    rowdot<<<(BB * LC) / 8, 256>>>(cout, sim_w, nullptr, cw, BB * LC);
    rowdot<<<(BB * LQ) / 8, 256>>>(qout, sim_w + H2, nullptr, qw, BB * LQ);
    attn_S<<<dim3(LC / 64, BB), 256>>>(cout, qout, sim_w, sim_b, cw, qw, S);
    softmax64<<<(BB * LC) / 8, 256>>>(S, smax, BB * LC);
    softmax512<<<BB, 512>>>(smax, batt);
    attn_c2q<<<dim3(H2 / 64, LC / 64, BB), 256>>>(S, qout, c2q);
    attn_q2c<<<dim3(H2 / 128, BB), 128>>>(batt, cout, q2c);
    build_G<<<(int)(((size_t)BB * LC * (H2 / 4) + 255) / 256), 256>>>(cout, c2q, q2c, G);

    // modeling BiLSTM (single group)
    cvt_tf32<<<(2 * G4 * H8 + 255) / 256, 256>>>(Wih_m, wcvt, 2 * G4 * H8);
    cvt_tf32<<<(2 * G4 * HH + 255) / 256, 256>>>(Whh_m, whh, 2 * G4 * HH);
    for (int d = 0; d < 2; ++d)
        gemm_tf32<<<dim3(G4 / 128, (BB * LC) / 128), 128, GEMM_SMEM>>>(
            G, wcvt + (size_t)d * G4 * H8, b_m + (size_t)d * G4,
            xw + (size_t)d * BB * LC * G4, BB * LC, G4, H8);
    lstm_scan2<<<64, 256, SCAN_SMEM>>>(xw, whh, M, LC, xw, whh, M, LC);

    // heads: one pass over M
    rowdot2<<<(BB * LC) / 8, 256>>>(M, start_w, start_b, end_w, end_b,
                                    out, out + (size_t)BB * LC, BB * LC);
}

// round 16
// speedup vs baseline: 1.3825x; 1.0512x over previous
#include <cuda_runtime.h>
#include <cuda_bf16.h>
#include <math.h>
#include <stdint.h>

#define EE   300
#define HH   256
#define G4   1024
#define H2   512
#define H8   2048
#define BB   64
#define LQ   64
#define LC   512

__device__ float g_qemb[(size_t)BB * LQ * EE];
__device__ float g_cemb[(size_t)BB * LC * EE];
__device__ float g_xw  [(size_t)2 * BB * LC * G4];
__device__ float g_xwq [(size_t)2 * BB * LQ * G4];
__device__ float g_qout[(size_t)BB * LQ * H2];
__device__ float g_cout[(size_t)BB * LC * H2];
__device__ float g_S   [(size_t)BB * LC * LQ];
__device__ float g_smax[(size_t)BB * LC];
__device__ float g_batt[(size_t)BB * LC];
__device__ float g_cw  [(size_t)BB * LC];
__device__ float g_qw  [(size_t)BB * LQ];
__device__ float g_c2q [(size_t)BB * LC * H2];
__device__ float g_q2c [(size_t)BB * H2];
__device__ float g_G   [(size_t)BB * LC * H8];
__device__ float g_M   [(size_t)BB * LC * H2];
__device__ float g_h   [(size_t)4 * HH * BB];
__device__ float g_wcvt[(size_t)2 * G4 * H8];
__device__ float g_whh [(size_t)4 * G4 * HH];
__device__ unsigned g_bar_cnt4[4] = {0, 0, 0, 0};
__device__ unsigned g_bar_gen4[4] = {0, 0, 0, 0};

__device__ __forceinline__ float sigmoidf_(float x) { return 1.f / (1.f + expf(-x)); }

__device__ __forceinline__ uint32_t f2tf32(float x)
{
    uint32_t r;
    asm("cvt.rna.tf32.f32 %0, %1;" : "=r"(r) : "f"(x));
    return r;
}
__device__ __forceinline__ float rtf(float x) { return __uint_as_float(f2tf32(x)); }

// Fence-lite grid barrier over a 32-block group (proxy-thread release/acquire).
__device__ __forceinline__ void grid_barrier_g(int grp, unsigned nb)
{
    __syncthreads();
    if (threadIdx.x == 0) {
        asm volatile("fence.acq_rel.gpu;" ::: "memory");
        unsigned g = *(volatile unsigned*)&g_bar_gen4[grp];
        if (atomicAdd(&g_bar_cnt4[grp], 1u) == nb - 1u) {
            g_bar_cnt4[grp] = 0;
            __threadfence();
            atomicAdd(&g_bar_gen4[grp], 1u);
        } else {
            while (*(volatile unsigned*)&g_bar_gen4[grp] == g) { }
        }
        asm volatile("fence.acq_rel.gpu;" ::: "memory");
    }
    __syncthreads();
}

__device__ __forceinline__ void cp16(uint32_t dst, const void* src)
{
    asm volatile("cp.async.cg.shared.global [%0], [%1], 16;" :: "r"(dst), "l"(src));
}
__device__ __forceinline__ uint32_t smem_u32(const void* p)
{
    uint32_t a;
    asm("{ .reg .u64 t; cvta.to.shared.u64 t, %1; cvt.u32.u64 %0, t; }" : "=r"(a) : "l"(p));
    return a;
}

// ---------------------------------------------------------------------------
__global__ void gather_emb(const int* __restrict__ tok, const float* __restrict__ emb,
                           float* __restrict__ out, int total)
{
    int i = blockIdx.x * blockDim.x + threadIdx.x;
    if (i >= total) return;
    int row = i / EE;
    int e   = i - row * EE;
    out[i] = rtf(emb[(size_t)tok[row] * EE + e]);
}

__global__ void cvt_tf32(const float* __restrict__ in, float* __restrict__ out, int n)
{
    int i = blockIdx.x * blockDim.x + threadIdx.x;
    if (i < n) out[i] = rtf(in[i]);
}

// ---------------------------------------------------------------------------
// tf32 mma.sync GEMM v4: CTA 128x128, 4 warps, warp 64x64, BK=32,
// 3-stage cp.async ring, one __syncthreads per k-tile.
// ---------------------------------------------------------------------------
#define SROW 36
#define STILE (128 * SROW)
#define GSTAGE (2 * STILE)
#define GEMM_SMEM (3 * GSTAGE * (int)sizeof(float))   // 110592 B

__device__ __forceinline__ void fill_tile(uint32_t sA, uint32_t sB,
                                          const float* __restrict__ A,
                                          const float* __restrict__ B,
                                          int bm, int bn, int K, int k0, int tid)
{
#pragma unroll
    for (int i = 0; i < 8; ++i) {
        int idx = tid + i * 128;
        int row = idx >> 3, c4 = idx & 7;
        int k = k0 + c4 * 4;
        uint32_t da = sA + (row * SROW + c4 * 4) * 4;
        uint32_t db = sB + (row * SROW + c4 * 4) * 4;
        if (k + 4 <= K) {
            cp16(da, &A[(size_t)(bm + row) * K + k]);
            cp16(db, &B[(size_t)(bn + row) * K + k]);
        } else {
            asm volatile("st.shared.v4.b32 [%0], {%1,%1,%1,%1};" :: "r"(da), "r"(0) : "memory");
            asm volatile("st.shared.v4.b32 [%0], {%1,%1,%1,%1};" :: "r"(db), "r"(0) : "memory");
        }
    }
}

__global__ void __launch_bounds__(128)
gemm_tf32(const float* __restrict__ A, const float* __restrict__ B,
          const float* __restrict__ bias, float* __restrict__ C,
          int M, int N, int K)
{
    extern __shared__ float sh[];
    const int tid  = threadIdx.x;
    const int lane = tid & 31;
    const int warp = tid >> 5;
    const int g = lane >> 2, t = lane & 3;
    const int m0 = (warp & 1) * 64;
    const int n0 = (warp >> 1) * 64;
    const int bm = blockIdx.y * 128;
    const int bn = blockIdx.x * 128;
    const uint32_t sb = smem_u32(sh);

    float acc[4][8][4];
#pragma unroll
    for (int mi = 0; mi < 4; ++mi)
#pragma unroll
        for (int ni = 0; ni < 8; ++ni)
#pragma unroll
            for (int k = 0; k < 4; ++k) acc[mi][ni][k] = 0.f;

    const int nk = (K + 31) >> 5;
    const uint32_t stage_b = GSTAGE * 4;

    fill_tile(sb, sb + STILE * 4, A, B, bm, bn, K, 0, tid);
    asm volatile("cp.async.commit_group;" ::: "memory");
    if (nk > 1)
        fill_tile(sb + stage_b, sb + stage_b + STILE * 4, A, B, bm, bn, K, 32, tid);
    asm volatile("cp.async.commit_group;" ::: "memory");

    for (int kt = 0; kt < nk; ++kt) {
        const int s = kt % 3;
        asm volatile("cp.async.wait_group 1;" ::: "memory");
        __syncthreads();
        if (kt + 2 < nk) {
            const int s2 = (kt + 2) % 3;
            fill_tile(sb + s2 * stage_b, sb + s2 * stage_b + STILE * 4,
                      A, B, bm, bn, K, (kt + 2) * 32, tid);
        }
        asm volatile("cp.async.commit_group;" ::: "memory");

        const float* Ab = sh + s * GSTAGE;
        const float* Bb = Ab + STILE;
#pragma unroll
        for (int kk = 0; kk < 32; kk += 8) {
            uint32_t af[4][4];
#pragma unroll
            for (int mi = 0; mi < 4; ++mi) {
                const float* ap = Ab + (m0 + mi * 16) * SROW + kk;
                af[mi][0] = __float_as_uint(ap[g * SROW + t]);
                af[mi][1] = __float_as_uint(ap[(g + 8) * SROW + t]);
                af[mi][2] = __float_as_uint(ap[g * SROW + t + 4]);
                af[mi][3] = __float_as_uint(ap[(g + 8) * SROW + t + 4]);
            }
            uint32_t bf[8][2];
#pragma unroll
            for (int ni = 0; ni < 8; ++ni) {
                const float* bp = Bb + (n0 + ni * 8) * SROW + kk;
                bf[ni][0] = __float_as_uint(bp[g * SROW + t]);
                bf[ni][1] = __float_as_uint(bp[g * SROW + t + 4]);
            }
#pragma unroll
            for (int mi = 0; mi < 4; ++mi)
#pragma unroll
                for (int ni = 0; ni < 8; ++ni)
                    asm volatile(
                        "mma.sync.aligned.m16n8k8.row.col.f32.tf32.tf32.f32 "
                        "{%0,%1,%2,%3}, {%4,%5,%6,%7}, {%8,%9}, {%0,%1,%2,%3};\n"
                        : "+f"(acc[mi][ni][0]), "+f"(acc[mi][ni][1]),
                          "+f"(acc[mi][ni][2]), "+f"(acc[mi][ni][3])
                        : "r"(af[mi][0]), "r"(af[mi][1]), "r"(af[mi][2]), "r"(af[mi][3]),
                          "r"(bf[ni][0]), "r"(bf[ni][1]));
        }
    }

#pragma unroll
    for (int mi = 0; mi < 4; ++mi) {
#pragma unroll
        for (int ni = 0; ni < 8; ++ni) {
            int row0 = bm + m0 + mi * 16 + g;
            int col  = bn + n0 + ni * 8 + t * 2;
            float2 bv = make_float2(0.f, 0.f);
            if (bias) bv = *(const float2*)&bias[col];
            *(float2*)&C[(size_t)row0 * N + col] =
                make_float2(acc[mi][ni][0] + bv.x, acc[mi][ni][1] + bv.y);
            *(float2*)&C[(size_t)(row0 + 8) * N + col] =
                make_float2(acc[mi][ni][2] + bv.x, acc[mi][ni][3] + bv.y);
        }
    }
}

// ---------------------------------------------------------------------------
// BiLSTM scan, tensor-core recurrence. Barrier group = blockIdx.x>>5 (32
// blocks = one direction chain); data group = blockIdx.x>>6. xW for step
// s+1 prefetched into registers before the barrier.
// ---------------------------------------------------------------------------
#define LPAD 72
#define SC_H   (HH * LPAD)
#define SC_XW  (SC_H + BB * 33)
#define SC_TOT (SC_XW + BB * 33)
#define SCAN_SMEM (SC_TOT * (int)sizeof(float))   // 90624 B

__global__ void __launch_bounds__(256)
lstm_scan2(const float* __restrict__ xW0, const float* __restrict__ Whh0,
           float* __restrict__ out0, int T0,
           const float* __restrict__ xW1, const float* __restrict__ Whh1,
           float* __restrict__ out1, int T1)
{
    extern __shared__ float sh[];
    float* h_sh  = sh;
    float* xw_sh = sh + SC_H;
    float* P_sh  = sh + SC_XW;

    const int tid  = threadIdx.x;
    const int lane = tid & 31;
    const int warp = tid >> 5;
    const int g = lane >> 2, t = lane & 3;
    const int nt  = warp >> 1;
    const int mtp = warp & 1;
    const int grp = blockIdx.x >> 6;          // data group
    const int bgr = blockIdx.x >> 5;          // barrier group (per dir)
    const int bid = blockIdx.x & 63;
    const int dir = bid >> 5;
    const int j0  = (bid & 31) * 8;

    const float* xWall = grp ? xW1 : xW0;
    const float* Whh   = grp ? Whh1 : Whh0;
    float*       outp  = grp ? out1 : out0;
    const int    T     = grp ? T1 : T0;

    float wreg[64];
    {
        const float* Wd = Whh + (size_t)dir * G4 * HH + (size_t)(nt * HH + j0 + g) * HH;
#pragma unroll
        for (int kt = 0; kt < 32; ++kt) {
            wreg[2 * kt]     = Wd[kt * 8 + t];
            wreg[2 * kt + 1] = Wd[kt * 8 + t + 4];
        }
    }

    const float* xWD = xWall + (size_t)dir * BB * T * G4;
    float*       hD  = g_h + (size_t)(grp * 2 + dir) * HH * BB;
    const int eb = tid & 63, eu = tid >> 6;
    float cst[2] = {0.f, 0.f};

    // prefetch xW for step 0
    float4 xv0, xv1;
    {
        const int tt0 = dir ? (T - 1) : 0;
        const float* src = &xWD[((size_t)eb * T + tt0) * G4 + eu * HH + j0];
        xv0 = *(const float4*)src;
        xv1 = *(const float4*)(src + 4);
    }

    for (int s = 0; s < T; ++s) {
        const int tt = dir ? (T - 1 - s) : s;
        {   // commit prefetched xW to smem
            float* d = &xw_sh[eb * 33 + eu * 8];
            d[0] = xv0.x; d[1] = xv0.y; d[2] = xv0.z; d[3] = xv0.w;
            d[4] = xv1.x; d[5] = xv1.y; d[6] = xv1.z; d[7] = xv1.w;
        }
        if (s > 0) {
            const float4* h4 = (const float4*)hD;
#pragma unroll
            for (int i = 0; i < 16; ++i) {
                int idx4 = tid + i * 256;
                int j = idx4 >> 4, b4 = (idx4 & 15) << 2;
                float4 v = __ldcg(h4 + idx4);
                *(float4*)&h_sh[j * LPAD + b4] = v;
            }
        }
        __syncthreads();

        float cf[2][4] = {{0.f, 0.f, 0.f, 0.f}, {0.f, 0.f, 0.f, 0.f}};
        if (s > 0) {
#pragma unroll
            for (int kt = 0; kt < 32; ++kt) {
                const float* hr0 = &h_sh[(kt * 8 + t) * LPAD];
                const float* hr1 = &h_sh[(kt * 8 + t + 4) * LPAD];
                uint32_t b0 = __float_as_uint(wreg[2 * kt]);
                uint32_t b1 = __float_as_uint(wreg[2 * kt + 1]);
#pragma unroll
                for (int p = 0; p < 2; ++p) {
                    int mb = mtp * 16 + p * 32;
                    uint32_t a0 = __float_as_uint(hr0[mb + g]);
                    uint32_t a1 = __float_as_uint(hr0[mb + g + 8]);
                    uint32_t a2 = __float_as_uint(hr1[mb + g]);
                    uint32_t a3 = __float_as_uint(hr1[mb + g + 8]);
                    asm volatile(
                        "mma.sync.aligned.m16n8k8.row.col.f32.tf32.tf32.f32 "
                        "{%0,%1,%2,%3}, {%4,%5,%6,%7}, {%8,%9}, {%0,%1,%2,%3};\n"
                        : "+f"(cf[p][0]), "+f"(cf[p][1]), "+f"(cf[p][2]), "+f"(cf[p][3])
                        : "r"(a0), "r"(a1), "r"(a2), "r"(a3), "r"(b0), "r"(b1));
                }
            }
        }
#pragma unroll
        for (int p = 0; p < 2; ++p) {
            int mb = mtp * 16 + p * 32;
            int cc = nt * 8 + 2 * t;
            P_sh[(mb + g) * 33 + cc]     = cf[p][0];
            P_sh[(mb + g) * 33 + cc + 1] = cf[p][1];
            P_sh[(mb + g + 8) * 33 + cc]     = cf[p][2];
            P_sh[(mb + g + 8) * 33 + cc + 1] = cf[p][3];
        }
        __syncthreads();

#pragma unroll
        for (int u = 0; u < 2; ++u) {
            int ju = eu + u * 4;
            const float* Pr = &P_sh[eb * 33];
            const float* Xr = &xw_sh[eb * 33];
            float pi = Pr[ju]      + Xr[ju];
            float pf = Pr[8 + ju]  + Xr[8 + ju];
            float pg = Pr[16 + ju] + Xr[16 + ju];
            float po = Pr[24 + ju] + Xr[24 + ju];
            float ig = sigmoidf_(pi);
            float fg = sigmoidf_(pf);
            float gg = tanhf(pg);
            float og = sigmoidf_(po);
            cst[u] = fg * cst[u] + ig * gg;
            float hh = og * tanhf(cst[u]);
            __stcg(&hD[(j0 + ju) * BB + eb], rtf(hh));
            outp[((size_t)eb * T + tt) * H2 + dir * HH + j0 + ju] = hh;
        }
        if (s + 1 < T) {
            {   // prefetch next step's xW before the barrier (hides L2 latency)
                const int tn = dir ? (T - 2 - s) : (s + 1);
                const float* src = &xWD[((size_t)eb * T + tn) * G4 + eu * HH + j0];
                xv0 = *(const float4*)src;
                xv1 = *(const float4*)(src + 4);
            }
            grid_barrier_g(bgr, 32);
        }
    }
}

// ---------------------------------------------------------------------------
__global__ void rowdot(const float* __restrict__ A, const float* __restrict__ w,
                       const float* __restrict__ bias, float* __restrict__ out, int rows)
{
    int gw = (blockIdx.x * blockDim.x + threadIdx.x) >> 5;
    int lane = threadIdx.x & 31;
    if (gw >= rows) return;
    const float* row = A + (size_t)gw * H2;
    float s = 0.f;
#pragma unroll
    for (int i = 0; i < 16; ++i) s += row[lane + i * 32] * w[lane + i * 32];
#pragma unroll
    for (int off = 16; off; off >>= 1) s += __shfl_xor_sync(0xffffffffu, s, off);
    if (lane == 0) out[gw] = s + (bias ? bias[0] : 0.f);
}

__global__ void rowdot2(const float* __restrict__ A,
                        const float* __restrict__ w0, const float* __restrict__ b0,
                        const float* __restrict__ w1, const float* __restrict__ b1,
                        float* __restrict__ o0, float* __restrict__ o1, int rows)
{
    int gw = (blockIdx.x * blockDim.x + threadIdx.x) >> 5;
    int lane = threadIdx.x & 31;
    if (gw >= rows) return;
    const float* row = A + (size_t)gw * H2;
    float s0 = 0.f, s1 = 0.f;
#pragma unroll
    for (int i = 0; i < 16; ++i) {
        float v = row[lane + i * 32];
        s0 += v * w0[lane + i * 32];
        s1 += v * w1[lane + i * 32];
    }
#pragma unroll
    for (int off = 16; off; off >>= 1) {
        s0 += __shfl_xor_sync(0xffffffffu, s0, off);
        s1 += __shfl_xor_sync(0xffffffffu, s1, off);
    }
    if (lane == 0) {
        o0[gw] = s0 + b0[0];
        o1[gw] = s1 + b1[0];
    }
}

__global__ void __launch_bounds__(256)
attn_S(const float* __restrict__ c_out, const float* __restrict__ q_out,
       const float* __restrict__ sim_w, const float* __restrict__ sim_b,
       const float* __restrict__ cw, const float* __restrict__ qw,
       float* __restrict__ S)
{
    __shared__ float As[16][68];
    __shared__ float Bs[16][68];
    const int b = blockIdx.y, cc0 = blockIdx.x * 64;
    const float* A  = c_out + ((size_t)b * LC + cc0) * H2;
    const float* Bq = q_out + (size_t)b * LQ * H2;
    const float* wcq = sim_w + 2 * H2;
    const int tid = threadIdx.x;
    const int lr = tid >> 2, lk4 = (tid & 3) * 4;
    const int tx = tid & 15, ty = tid >> 4;
    float acc[4][4];
#pragma unroll
    for (int i = 0; i < 4; ++i)
#pragma unroll
        for (int j = 0; j < 4; ++j) acc[i][j] = 0.f;

    for (int k0 = 0; k0 < H2; k0 += 16) {
        float4 va = *(const float4*)&A[(size_t)lr * H2 + k0 + lk4];
        float4 wv = *(const float4*)&wcq[k0 + lk4];
        As[lk4 + 0][lr] = va.x * wv.x;
        As[lk4 + 1][lr] = va.y * wv.y;
        As[lk4 + 2][lr] = va.z * wv.z;
        As[lk4 + 3][lr] = va.w * wv.w;
        float4 vb = *(const float4*)&Bq[(size_t)lr * H2 + k0 + lk4];
        Bs[lk4 + 0][lr] = vb.x;
        Bs[lk4 + 1][lr] = vb.y;
        Bs[lk4 + 2][lr] = vb.z;
        Bs[lk4 + 3][lr] = vb.w;
        __syncthreads();
#pragma unroll
        for (int k = 0; k < 16; ++k) {
            float4 av = *(const float4*)&As[k][ty * 4];
            float4 bv = *(const float4*)&Bs[k][tx * 4];
            float am[4] = {av.x, av.y, av.z, av.w};
            float bn[4] = {bv.x, bv.y, bv.z, bv.w};
#pragma unroll
            for (int i = 0; i < 4; ++i)
#pragma unroll
                for (int j = 0; j < 4; ++j) acc[i][j] += am[i] * bn[j];
        }
        __syncthreads();
    }
    float sb = sim_b[0];
#pragma unroll
    for (int i = 0; i < 4; ++i) {
        int cc = cc0 + ty * 4 + i;
        float cwv = cw[b * LC + cc];
#pragma unroll
        for (int j = 0; j < 4; ++j) {
            int qq = tx * 4 + j;
            S[((size_t)b * LC + cc) * LQ + qq] = acc[i][j] + cwv + qw[b * LQ + qq] + sb;
        }
    }
}

__global__ void softmax64(float* __restrict__ S, float* __restrict__ smax, int rows)
{
    int gw = (blockIdx.x * blockDim.x + threadIdx.x) >> 5;
    int lane = threadIdx.x & 31;
    if (gw >= rows) return;
    float* row = S + (size_t)gw * LQ;
    float v0 = row[lane], v1 = row[lane + 32];
    float m = fmaxf(v0, v1);
#pragma unroll
    for (int off = 16; off; off >>= 1) m = fmaxf(m, __shfl_xor_sync(0xffffffffu, m, off));
    float e0 = expf(v0 - m), e1 = expf(v1 - m);
    float s = e0 + e1;
#pragma unroll
    for (int off = 16; off; off >>= 1) s += __shfl_xor_sync(0xffffffffu, s, off);
    float inv = 1.f / s;
    row[lane] = e0 * inv;
    row[lane + 32] = e1 * inv;
    if (lane == 0) smax[gw] = m;
}

__global__ void softmax512(const float* __restrict__ in, float* __restrict__ outv)
{
    __shared__ float red[16];
    int b = blockIdx.x, tid = threadIdx.x;
    float v = in[(size_t)b * LC + tid];
    float m = v;
#pragma unroll
    for (int off = 16; off; off >>= 1) m = fmaxf(m, __shfl_xor_sync(0xffffffffu, m, off));
    if ((tid & 31) == 0) red[tid >> 5] = m;
    __syncthreads();
    if (tid == 0) {
        float x = red[0];
        for (int i = 1; i < 16; ++i) x = fmaxf(x, red[i]);
        red[0] = x;
    }
    __syncthreads();
    m = red[0];
    __syncthreads();
    float e = expf(v - m);
    float s = e;
#pragma unroll
    for (int off = 16; off; off >>= 1) s += __shfl_xor_sync(0xffffffffu, s, off);
    if ((tid & 31) == 0) red[tid >> 5] = s;
    __syncthreads();
    if (tid == 0) {
        float x = 0.f;
        for (int i = 0; i < 16; ++i) x += red[i];
        red[0] = x;
    }
    __syncthreads();
    outv[(size_t)b * LC + tid] = e / red[0];
}

__global__ void __launch_bounds__(256)
attn_c2q(const float* __restrict__ a, const float* __restrict__ q_out,
         float* __restrict__ c2q)
{
    __shared__ float As[16][68];
    __shared__ float Bs[16][68];
    const int b = blockIdx.z, cc0 = blockIdx.y * 64, h0 = blockIdx.x * 64;
    const float* A = a + ((size_t)b * LC + cc0) * LQ;
    const float* B = q_out + (size_t)b * LQ * H2;
    const int tid = threadIdx.x;
    const int lr = tid >> 2, lk4 = (tid & 3) * 4;
    const int bk = tid >> 4, bn4 = (tid & 15) * 4;
    const int tx = tid & 15, ty = tid >> 4;
    float acc[4][4];
#pragma unroll
    for (int i = 0; i < 4; ++i)
#pragma unroll
        for (int j = 0; j < 4; ++j) acc[i][j] = 0.f;

    for (int k0 = 0; k0 < LQ; k0 += 16) {
        float4 va = *(const float4*)&A[(size_t)lr * LQ + k0 + lk4];
        As[lk4 + 0][lr] = va.x;
        As[lk4 + 1][lr] = va.y;
        As[lk4 + 2][lr] = va.z;
        As[lk4 + 3][lr] = va.w;
        float4 vb = *(const float4*)&B[(size_t)(k0 + bk) * H2 + h0 + bn4];
        *(float4*)&Bs[bk][bn4] = vb;
        __syncthreads();
#pragma unroll
        for (int k = 0; k < 16; ++k) {
            float4 av = *(const float4*)&As[k][ty * 4];
            float4 bv = *(const float4*)&Bs[k][tx * 4];
            float am[4] = {av.x, av.y, av.z, av.w};
            float bn[4] = {bv.x, bv.y, bv.z, bv.w};
#pragma unroll
            for (int i = 0; i < 4; ++i)
#pragma unroll
                for (int j = 0; j < 4; ++j) acc[i][j] += am[i] * bn[j];
        }
        __syncthreads();
    }
#pragma unroll
    for (int i = 0; i < 4; ++i)
#pragma unroll
        for (int j = 0; j < 4; ++j)
            c2q[((size_t)b * LC + cc0 + ty * 4 + i) * H2 + h0 + tx * 4 + j] = acc[i][j];
}

__global__ void attn_q2c(const float* __restrict__ batt, const float* __restrict__ c_out,
                         float* __restrict__ q2c)
{
    int b = blockIdx.y;
    int h = blockIdx.x * 128 + threadIdx.x;
    const float* C = c_out + (size_t)b * LC * H2;
    const float* w = batt + (size_t)b * LC;
    float acc = 0.f;
    for (int cc = 0; cc < LC; ++cc) acc += w[cc] * C[(size_t)cc * H2 + h];
    q2c[(size_t)b * H2 + h] = acc;
}

__global__ void build_G(const float* __restrict__ c_out, const float* __restrict__ c2q,
                        const float* __restrict__ q2c, float* __restrict__ G)
{
    size_t i = (size_t)blockIdx.x * blockDim.x + threadIdx.x;
    const size_t total = (size_t)BB * LC * (H2 / 4);
    if (i >= total) return;
    int h4 = (int)(i % (H2 / 4));
    size_t r = i / (H2 / 4);
    int b = (int)(r / LC);
    float4 co = ((const float4*)c_out)[r * (H2 / 4) + h4];
    float4 cq = ((const float4*)c2q)[r * (H2 / 4) + h4];
    float4 q2 = ((const float4*)q2c)[(size_t)b * (H2 / 4) + h4];
    float4* Gr = (float4*)(G + r * H8);
    Gr[h4] = make_float4(rtf(co.x), rtf(co.y), rtf(co.z), rtf(co.w));
    Gr[(H2 / 4) + h4] = make_float4(rtf(cq.x), rtf(cq.y), rtf(cq.z), rtf(cq.w));
    Gr[2 * (H2 / 4) + h4] = make_float4(rtf(co.x * cq.x), rtf(co.y * cq.y),
                                        rtf(co.z * cq.z), rtf(co.w * cq.w));
    Gr[3 * (H2 / 4) + h4] = make_float4(rtf(co.x * q2.x), rtf(co.y * q2.y),
                                        rtf(co.z * q2.z), rtf(co.w * q2.w));
}

// ---------------------------------------------------------------------------
extern "C" void kernel_launch(void* const* d_in, const int* in_sizes, int n_in,
                              void* d_out, int out_size)
{
    const int*   q       = (const int*)  d_in[0];
    const int*   c       = (const int*)  d_in[1];
    const float* emb     = (const float*)d_in[2];
    const float* Wih_q   = (const float*)d_in[3];
    const float* Whh_q   = (const float*)d_in[4];
    const float* b_q     = (const float*)d_in[5];
    const float* Wih_c   = (const float*)d_in[6];
    const float* Whh_c   = (const float*)d_in[7];
    const float* b_c     = (const float*)d_in[8];
    const float* Wih_m   = (const float*)d_in[9];
    const float* Whh_m   = (const float*)d_in[10];
    const float* b_m     = (const float*)d_in[11];
    const float* sim_w   = (const float*)d_in[12];
    const float* sim_b   = (const float*)d_in[13];
    const float* start_w = (const float*)d_in[14];
    const float* start_b = (const float*)d_in[15];
    const float* end_w   = (const float*)d_in[16];
    const float* end_b   = (const float*)d_in[17];
    float* out = (float*)d_out;

    float *qemb, *cemb, *xw, *xwq, *qout, *cout, *S, *smax, *batt, *cw, *qw, *c2q, *q2c, *G, *M, *wcvt, *whh;
    cudaGetSymbolAddress((void**)&qemb, g_qemb);
    cudaGetSymbolAddress((void**)&cemb, g_cemb);
    cudaGetSymbolAddress((void**)&xw,   g_xw);
    cudaGetSymbolAddress((void**)&xwq,  g_xwq);
    cudaGetSymbolAddress((void**)&qout, g_qout);
    cudaGetSymbolAddress((void**)&cout, g_cout);
    cudaGetSymbolAddress((void**)&S,    g_S);
    cudaGetSymbolAddress((void**)&smax, g_smax);
    cudaGetSymbolAddress((void**)&batt, g_batt);
    cudaGetSymbolAddress((void**)&cw,   g_cw);
    cudaGetSymbolAddress((void**)&qw,   g_qw);
    cudaGetSymbolAddress((void**)&c2q,  g_c2q);
    cudaGetSymbolAddress((void**)&q2c,  g_q2c);
    cudaGetSymbolAddress((void**)&G,    g_G);
    cudaGetSymbolAddress((void**)&M,    g_M);
    cudaGetSymbolAddress((void**)&wcvt, g_wcvt);
    cudaGetSymbolAddress((void**)&whh,  g_whh);

    cudaFuncSetAttribute(lstm_scan2, cudaFuncAttributeMaxDynamicSharedMemorySize, SCAN_SMEM);
    cudaFuncSetAttribute(gemm_tf32, cudaFuncAttributeMaxDynamicSharedMemorySize, GEMM_SMEM);

    gather_emb<<<(BB * LQ * EE + 255) / 256, 256>>>(q, emb, qemb, BB * LQ * EE);
    gather_emb<<<(BB * LC * EE + 255) / 256, 256>>>(c, emb, cemb, BB * LC * EE);

    cvt_tf32<<<(2 * G4 * EE + 255) / 256, 256>>>(Wih_q, wcvt, 2 * G4 * EE);
    cvt_tf32<<<(2 * G4 * HH + 255) / 256, 256>>>(Whh_q, whh + (size_t)2 * G4 * HH, 2 * G4 * HH);
    for (int d = 0; d < 2; ++d)
        gemm_tf32<<<dim3(G4 / 128, (BB * LQ) / 128), 128, GEMM_SMEM>>>(
            qemb, wcvt + (size_t)d * G4 * EE, b_q + (size_t)d * G4,
            xwq + (size_t)d * BB * LQ * G4, BB * LQ, G4, EE);
    cvt_tf32<<<(2 * G4 * EE + 255) / 256, 256>>>(Wih_c, wcvt, 2 * G4 * EE);
    cvt_tf32<<<(2 * G4 * HH + 255) / 256, 256>>>(Whh_c, whh, 2 * G4 * HH);
    for (int d = 0; d < 2; ++d)
        gemm_tf32<<<dim3(G4 / 128, (BB * LC) / 128), 128, GEMM_SMEM>>>(
            cemb, wcvt + (size_t)d * G4 * EE, b_c + (size_t)d * G4,
            xw + (size_t)d * BB * LC * G4, BB * LC, G4, EE);
    lstm_scan2<<<128, 256, SCAN_SMEM>>>(xw, whh, cout, LC,
                                        xwq, whh + (size_t)2 * G4 * HH, qout, LQ);

    rowdot<<<(BB * LC) / 8, 256>>>(cout, sim_w, nullptr, cw, BB * LC);
    rowdot<<<(BB * LQ) / 8, 256>>>(qout, sim_w + H2, nullptr, qw, BB * LQ);
    attn_S<<<dim3(LC / 64, BB), 256>>>(cout, qout, sim_w, sim_b, cw, qw, S);
    softmax64<<<(BB * LC) / 8, 256>>>(S, smax, BB * LC);
    softmax512<<<BB, 512>>>(smax, batt);
    attn_c2q<<<dim3(H2 / 64, LC / 64, BB), 256>>>(S, qout, c2q);
    attn_q2c<<<dim3(H2 / 128, BB), 128>>>(batt, cout, q2c);
    build_G<<<(int)(((size_t)BB * LC * (H2 / 4) + 255) / 256), 256>>>(cout, c2q, q2c, G);

    cvt_tf32<<<(2 * G4 * H8 + 255) / 256, 256>>>(Wih_m, wcvt, 2 * G4 * H8);
    cvt_tf32<<<(2 * G4 * HH + 255) / 256, 256>>>(Whh_m, whh, 2 * G4 * HH);
    for (int d = 0; d < 2; ++d)
        gemm_tf32<<<dim3(G4 / 128, (BB * LC) / 128), 128, GEMM_SMEM>>>(
            G, wcvt + (size_t)d * G4 * H8, b_m + (size_t)d * G4,
            xw + (size_t)d * BB * LC * G4, BB * LC, G4, H8);
    lstm_scan2<<<64, 256, SCAN_SMEM>>>(xw, whh, M, LC, xw, whh, M, LC);

    rowdot2<<<(BB * LC) / 8, 256>>>(M, start_w, start_b, end_w, end_b,
                                    out, out + (size_t)BB * LC, BB * LC);
}